// round 1
// baseline (speedup 1.0000x reference)
#include <cuda_runtime.h>
#include <math.h>

// Problem constants (fixed by the reference: B=4, C=512, H=W=64)
#define C_DIM 512
#define N_DIM 4096
#define MAXB  4

// -------- scratch (__device__ globals: zero-init, no runtime allocation) -----
__device__ float g_xn  [MAXB * C_DIM * N_DIM];   // 33.5 MB
__device__ float g_q   [MAXB * C_DIM * N_DIM];
__device__ float g_k   [MAXB * C_DIM * N_DIM];
__device__ float g_v   [MAXB * C_DIM * N_DIM];
__device__ float g_o   [MAXB * C_DIM * N_DIM];
__device__ float g_attn[MAXB * (size_t)N_DIM * N_DIM];  // 268 MB

// ============================================================================
// GroupNorm: 32 groups, 16 channels/group, eps=1e-5
// One block per (batch, group). CNT = 16*4096 = 65536 elements.
// ============================================================================
__global__ void groupnorm_kernel(const float* __restrict__ x,
                                 const float* __restrict__ w,
                                 const float* __restrict__ b,
                                 float* __restrict__ out)
{
    const int CPG = 16;
    const int CNT = CPG * N_DIM;        // 65536
    int bg = blockIdx.x;
    int g  = bg & 31;
    int bb = bg >> 5;
    size_t base = ((size_t)bb * C_DIM + (size_t)g * CPG) * N_DIM;
    const float4* x4 = (const float4*)(x + base);
    float4*       o4 = (float4*)(out + base);
    int tid = threadIdx.x;

    float s = 0.f, ss = 0.f;
    for (int i = tid; i < CNT / 4; i += blockDim.x) {
        float4 v = x4[i];
        s  += v.x + v.y + v.z + v.w;
        ss += v.x*v.x + v.y*v.y + v.z*v.z + v.w*v.w;
    }
    __shared__ float rs[8], rss[8];
    #pragma unroll
    for (int o = 16; o; o >>= 1) {
        s  += __shfl_xor_sync(0xffffffffu, s,  o);
        ss += __shfl_xor_sync(0xffffffffu, ss, o);
    }
    int wid = tid >> 5, lid = tid & 31;
    if (!lid) { rs[wid] = s; rss[wid] = ss; }
    __syncthreads();
    if (tid == 0) {
        float ts = 0.f, tss = 0.f;
        int nw = blockDim.x >> 5;
        for (int i = 0; i < nw; i++) { ts += rs[i]; tss += rss[i]; }
        rs[0] = ts; rss[0] = tss;
    }
    __syncthreads();
    float mu  = rs[0] / (float)CNT;
    float var = rss[0] / (float)CNT - mu * mu;
    float rsig = rsqrtf(var + 1e-5f);

    for (int i = tid; i < CNT / 4; i += blockDim.x) {
        int c = g * CPG + (i >> 10);            // i*4/4096
        float sc = w[c] * rsig;
        float sh = b[c] - mu * sc;
        float4 v = x4[i];
        v.x = v.x * sc + sh;
        v.y = v.y * sc + sh;
        v.z = v.z * sc + sh;
        v.w = v.w * sc + sh;
        o4[i] = v;
    }
}

// ============================================================================
// Generic tiled SGEMM: C[m,n] = alpha * sum_k A(m,k)*B(k,n) (+bias[m]) (+res)
//   TA=false: A stored [M x K] row-major (lda = k-stride of row m)
//   TA=true : A stored [K x M] k-major   (lda = m-row length)
//   TB=false: B stored [K x N] k-major   (ldb = n-row length)
//   TB=true : B stored [N x K] n-major   (ldb = k-row length)
// BM=BN=128, BK=16, 256 threads, 8x8 per-thread microtile.
// All dims assumed multiples of tile sizes (true for this problem).
// ============================================================================
template <bool TA, bool TB>
__global__ __launch_bounds__(256)
void sgemm_kernel(const float* __restrict__ A, const float* __restrict__ B,
                  float* __restrict__ C,
                  int M, int N, int K, int lda, int ldb, int ldc,
                  long long sA, long long sB, long long sC,
                  const float* __restrict__ bias,
                  const float* __restrict__ res, long long sRes,
                  float alpha)
{
    const int BM = 128, BN = 128, BK = 16;
    __shared__ float As[BK][BM + 4];
    __shared__ float Bs[BK][BN + 4];

    int z = blockIdx.z;
    A += (long long)z * sA;
    B += (long long)z * sB;
    C += (long long)z * sC;
    if (res) res += (long long)z * sRes;

    int m0 = blockIdx.y * BM;
    int n0 = blockIdx.x * BN;
    int tid = threadIdx.x;

    float acc[8][8];
    #pragma unroll
    for (int i = 0; i < 8; i++)
        #pragma unroll
        for (int j = 0; j < 8; j++) acc[i][j] = 0.f;

    for (int k0 = 0; k0 < K; k0 += BK) {
        // ---- load A tile into As[k][m] ----
        if (TA) {
            #pragma unroll
            for (int r = 0; r < 2; r++) {
                int i  = tid + r * 256;         // 512 float4
                int k  = i >> 5;                // 32 float4 per k-row
                int mq = (i & 31) << 2;
                float4 v = *(const float4*)&A[(size_t)(k0 + k) * lda + m0 + mq];
                *(float4*)&As[k][mq] = v;
            }
        } else {
            #pragma unroll
            for (int r = 0; r < 2; r++) {
                int i  = tid + r * 256;
                int m  = i >> 2;                // 4 float4 per m-row
                int kq = (i & 3) << 2;
                float4 v = *(const float4*)&A[(size_t)(m0 + m) * lda + k0 + kq];
                As[kq + 0][m] = v.x;
                As[kq + 1][m] = v.y;
                As[kq + 2][m] = v.z;
                As[kq + 3][m] = v.w;
            }
        }
        // ---- load B tile into Bs[k][n] ----
        if (!TB) {
            #pragma unroll
            for (int r = 0; r < 2; r++) {
                int i  = tid + r * 256;
                int k  = i >> 5;
                int nq = (i & 31) << 2;
                float4 v = *(const float4*)&B[(size_t)(k0 + k) * ldb + n0 + nq];
                *(float4*)&Bs[k][nq] = v;
            }
        } else {
            #pragma unroll
            for (int r = 0; r < 2; r++) {
                int i  = tid + r * 256;
                int n  = i >> 2;
                int kq = (i & 3) << 2;
                float4 v = *(const float4*)&B[(size_t)(n0 + n) * ldb + k0 + kq];
                Bs[kq + 0][n] = v.x;
                Bs[kq + 1][n] = v.y;
                Bs[kq + 2][n] = v.z;
                Bs[kq + 3][n] = v.w;
            }
        }
        __syncthreads();

        int ty = tid >> 4, tx = tid & 15;
        #pragma unroll
        for (int k = 0; k < BK; k++) {
            float4 a0 = *(const float4*)&As[k][ty * 8];
            float4 a1 = *(const float4*)&As[k][ty * 8 + 4];
            float4 b0 = *(const float4*)&Bs[k][tx * 8];
            float4 b1 = *(const float4*)&Bs[k][tx * 8 + 4];
            float av[8] = {a0.x, a0.y, a0.z, a0.w, a1.x, a1.y, a1.z, a1.w};
            float bv[8] = {b0.x, b0.y, b0.z, b0.w, b1.x, b1.y, b1.z, b1.w};
            #pragma unroll
            for (int i = 0; i < 8; i++)
                #pragma unroll
                for (int j = 0; j < 8; j++)
                    acc[i][j] += av[i] * bv[j];
        }
        __syncthreads();
    }

    // ---- epilogue ----
    int ty = tid >> 4, tx = tid & 15;
    #pragma unroll
    for (int i = 0; i < 8; i++) {
        int m = m0 + ty * 8 + i;
        float bi = bias ? bias[m] : 0.f;
        size_t off = (size_t)m * ldc + n0 + tx * 8;
        float4 o0, o1;
        o0.x = acc[i][0] * alpha + bi;
        o0.y = acc[i][1] * alpha + bi;
        o0.z = acc[i][2] * alpha + bi;
        o0.w = acc[i][3] * alpha + bi;
        o1.x = acc[i][4] * alpha + bi;
        o1.y = acc[i][5] * alpha + bi;
        o1.z = acc[i][6] * alpha + bi;
        o1.w = acc[i][7] * alpha + bi;
        if (res) {
            float4 r0 = *(const float4*)&res[off];
            float4 r1 = *(const float4*)&res[off + 4];
            o0.x += r0.x; o0.y += r0.y; o0.z += r0.z; o0.w += r0.w;
            o1.x += r1.x; o1.y += r1.y; o1.z += r1.z; o1.w += r1.w;
        }
        *(float4*)&C[off]     = o0;
        *(float4*)&C[off + 4] = o1;
    }
}

// ============================================================================
// Row softmax over attn[b, i, :] (row length N_DIM=4096). 256 threads/row.
// ============================================================================
__global__ void softmax_kernel(float* __restrict__ attn)
{
    size_t row = blockIdx.x;
    float4* p = (float4*)(attn + row * N_DIM);
    int tid = threadIdx.x;
    __shared__ float sh[8];

    float4 r[4];
    float mx = -1e30f;
    #pragma unroll
    for (int i = 0; i < 4; i++) {
        r[i] = p[tid + i * 256];
        mx = fmaxf(mx, fmaxf(fmaxf(r[i].x, r[i].y), fmaxf(r[i].z, r[i].w)));
    }
    // block max
    #pragma unroll
    for (int o = 16; o; o >>= 1) mx = fmaxf(mx, __shfl_xor_sync(0xffffffffu, mx, o));
    if ((tid & 31) == 0) sh[tid >> 5] = mx;
    __syncthreads();
    if (tid == 0) {
        float t = sh[0];
        for (int i = 1; i < 8; i++) t = fmaxf(t, sh[i]);
        sh[0] = t;
    }
    __syncthreads();
    mx = sh[0];
    __syncthreads();

    float sum = 0.f;
    #pragma unroll
    for (int i = 0; i < 4; i++) {
        r[i].x = __expf(r[i].x - mx);
        r[i].y = __expf(r[i].y - mx);
        r[i].z = __expf(r[i].z - mx);
        r[i].w = __expf(r[i].w - mx);
        sum += r[i].x + r[i].y + r[i].z + r[i].w;
    }
    #pragma unroll
    for (int o = 16; o; o >>= 1) sum += __shfl_xor_sync(0xffffffffu, sum, o);
    if ((tid & 31) == 0) sh[tid >> 5] = sum;
    __syncthreads();
    if (tid == 0) {
        float t = 0.f;
        for (int i = 0; i < 8; i++) t += sh[i];
        sh[0] = t;
    }
    __syncthreads();
    float inv = 1.f / sh[0];

    #pragma unroll
    for (int i = 0; i < 4; i++) {
        r[i].x *= inv; r[i].y *= inv; r[i].z *= inv; r[i].w *= inv;
        p[tid + i * 256] = r[i];
    }
}

// ============================================================================
// Host launcher
// ============================================================================
extern "C" void kernel_launch(void* const* d_in, const int* in_sizes, int n_in,
                              void* d_out, int out_size)
{
    const float* x   = (const float*)d_in[0];
    const float* gnw = (const float*)d_in[1];
    const float* gnb = (const float*)d_in[2];
    const float* wq  = (const float*)d_in[3];
    const float* bq  = (const float*)d_in[4];
    const float* wk  = (const float*)d_in[5];
    const float* bk  = (const float*)d_in[6];
    const float* wv  = (const float*)d_in[7];
    const float* bv  = (const float*)d_in[8];
    const float* wp  = (const float*)d_in[9];
    const float* bp  = (const float*)d_in[10];
    float* out = (float*)d_out;

    int B = in_sizes[0] / (C_DIM * N_DIM);
    if (B < 1) B = 1;
    if (B > MAXB) B = MAXB;

    float *p_xn, *p_q, *p_k, *p_v, *p_o, *p_attn;
    cudaGetSymbolAddress((void**)&p_xn,   g_xn);
    cudaGetSymbolAddress((void**)&p_q,    g_q);
    cudaGetSymbolAddress((void**)&p_k,    g_k);
    cudaGetSymbolAddress((void**)&p_v,    g_v);
    cudaGetSymbolAddress((void**)&p_o,    g_o);
    cudaGetSymbolAddress((void**)&p_attn, g_attn);

    const long long CN = (long long)C_DIM * N_DIM;
    const long long NN = (long long)N_DIM * N_DIM;
    const float scale = 1.0f / sqrtf((float)C_DIM);

    // 1) GroupNorm -> g_xn
    groupnorm_kernel<<<B * 32, 256>>>(x, gnw, gnb, p_xn);

    // 2) Q/K/V projections: [512x512] @ [512x4096] per batch
    {
        dim3 grid(N_DIM / 128, C_DIM / 128, B);
        sgemm_kernel<false, false><<<grid, 256>>>(wq, p_xn, p_q,
            C_DIM, N_DIM, C_DIM, C_DIM, N_DIM, N_DIM,
            0, CN, CN, bq, nullptr, 0, 1.0f);
        sgemm_kernel<false, false><<<grid, 256>>>(wk, p_xn, p_k,
            C_DIM, N_DIM, C_DIM, C_DIM, N_DIM, N_DIM,
            0, CN, CN, bk, nullptr, 0, 1.0f);
        sgemm_kernel<false, false><<<grid, 256>>>(wv, p_xn, p_v,
            C_DIM, N_DIM, C_DIM, C_DIM, N_DIM, N_DIM,
            0, CN, CN, bv, nullptr, 0, 1.0f);
    }

    // 3) Scores: S[i,j] = scale * sum_c q[c,i] k[c,j]   (M=N=4096, K=512)
    {
        dim3 grid(N_DIM / 128, N_DIM / 128, B);
        sgemm_kernel<true, false><<<grid, 256>>>(p_q, p_k, p_attn,
            N_DIM, N_DIM, C_DIM, N_DIM, N_DIM, N_DIM,
            CN, CN, NN, nullptr, nullptr, 0, scale);
    }

    // 4) Softmax over each row of attn
    softmax_kernel<<<B * N_DIM, 256>>>(p_attn);

    // 5) out[c,i] = sum_j v[c,j] * P[i,j]   (M=512, N=4096, K=4096)
    {
        dim3 grid(N_DIM / 128, C_DIM / 128, B);
        sgemm_kernel<false, true><<<grid, 256>>>(p_v, p_attn, p_o,
            C_DIM, N_DIM, N_DIM, N_DIM, N_DIM, N_DIM,
            CN, NN, CN, nullptr, nullptr, 0, 1.0f);
    }

    // 6) Projection + bias + residual -> d_out
    {
        dim3 grid(N_DIM / 128, C_DIM / 128, B);
        sgemm_kernel<false, false><<<grid, 256>>>(wp, p_o, out,
            C_DIM, N_DIM, C_DIM, C_DIM, N_DIM, N_DIM,
            0, CN, CN, bp, x, CN, 1.0f);
    }
}

// round 3
// speedup vs baseline: 1.6180x; 1.6180x over previous
#include <cuda_runtime.h>
#include <cuda_bf16.h>
#include <stdint.h>
#include <math.h>

typedef unsigned int u32;

// Problem constants (fixed by the reference: B=4, C=512, H=W=64)
#define C_DIM 512
#define N_DIM 4096
#define MAXB  4

// -------- scratch (__device__ globals: zero-init, no runtime allocation) -----
__device__ float g_xn  [MAXB * C_DIM * N_DIM];
__device__ float g_q   [MAXB * C_DIM * N_DIM];
__device__ float g_k   [MAXB * C_DIM * N_DIM];
__device__ float g_v   [MAXB * C_DIM * N_DIM];
__device__ float g_o   [MAXB * C_DIM * N_DIM];
__device__ float g_attn[MAXB * (size_t)N_DIM * N_DIM];  // 268 MB

// ============================================================================
// Helpers: bf16 split + ldmatrix + mma
// ============================================================================
__device__ __forceinline__ u32 pack_bf(__nv_bfloat16 x, __nv_bfloat16 y)
{
    __nv_bfloat162 t(x, y);
    return *(u32*)&t;
}

__device__ __forceinline__ void split4(float4 v, u32& h0, u32& h1,
                                       u32& l0, u32& l1)
{
    __nv_bfloat16 hx = __float2bfloat16(v.x);
    __nv_bfloat16 hy = __float2bfloat16(v.y);
    __nv_bfloat16 hz = __float2bfloat16(v.z);
    __nv_bfloat16 hw = __float2bfloat16(v.w);
    __nv_bfloat16 lx = __float2bfloat16(v.x - __bfloat162float(hx));
    __nv_bfloat16 ly = __float2bfloat16(v.y - __bfloat162float(hy));
    __nv_bfloat16 lz = __float2bfloat16(v.z - __bfloat162float(hz));
    __nv_bfloat16 lw = __float2bfloat16(v.w - __bfloat162float(hw));
    h0 = pack_bf(hx, hy);
    h1 = pack_bf(hz, hw);
    l0 = pack_bf(lx, ly);
    l1 = pack_bf(lz, lw);
}

__device__ __forceinline__ u32 saddr(const void* p)
{
    return (u32)__cvta_generic_to_shared(p);
}

__device__ __forceinline__ void ldsm4(u32* r, u32 a)
{
    asm volatile("ldmatrix.sync.aligned.m8n8.x4.shared.b16 {%0,%1,%2,%3}, [%4];\n"
        : "=r"(r[0]), "=r"(r[1]), "=r"(r[2]), "=r"(r[3]) : "r"(a));
}

__device__ __forceinline__ void ldsm4t(u32* r, u32 a)
{
    asm volatile("ldmatrix.sync.aligned.m8n8.x4.trans.shared.b16 {%0,%1,%2,%3}, [%4];\n"
        : "=r"(r[0]), "=r"(r[1]), "=r"(r[2]), "=r"(r[3]) : "r"(a));
}

__device__ __forceinline__ void mma_bf16(float* c, const u32* a, u32 b0, u32 b1)
{
    asm volatile(
        "mma.sync.aligned.m16n8k16.row.col.f32.bf16.bf16.f32 "
        "{%0,%1,%2,%3}, {%4,%5,%6,%7}, {%8,%9}, {%0,%1,%2,%3};\n"
        : "+f"(c[0]), "+f"(c[1]), "+f"(c[2]), "+f"(c[3])
        : "r"(a[0]), "r"(a[1]), "r"(a[2]), "r"(a[3]), "r"(b0), "r"(b1));
}

// ============================================================================
// GroupNorm: 32 groups, 16 ch/group, eps=1e-5. One block per (batch,group).
// ============================================================================
__global__ void groupnorm_kernel(const float* __restrict__ x,
                                 const float* __restrict__ w,
                                 const float* __restrict__ b,
                                 float* __restrict__ out)
{
    const int CPG = 16;
    const int CNT = CPG * N_DIM;
    int bg = blockIdx.x;
    int g  = bg & 31;
    int bb = bg >> 5;
    size_t base = ((size_t)bb * C_DIM + (size_t)g * CPG) * N_DIM;
    const float4* x4 = (const float4*)(x + base);
    float4*       o4 = (float4*)(out + base);
    int tid = threadIdx.x;

    float s = 0.f, ss = 0.f;
    for (int i = tid; i < CNT / 4; i += blockDim.x) {
        float4 v = x4[i];
        s  += v.x + v.y + v.z + v.w;
        ss += v.x * v.x + v.y * v.y + v.z * v.z + v.w * v.w;
    }
    __shared__ float rs[8], rss[8];
    #pragma unroll
    for (int o = 16; o; o >>= 1) {
        s  += __shfl_xor_sync(0xffffffffu, s,  o);
        ss += __shfl_xor_sync(0xffffffffu, ss, o);
    }
    int wid = tid >> 5;
    int lid = tid & 31;
    if (lid == 0) { rs[wid] = s; rss[wid] = ss; }
    __syncthreads();
    if (tid == 0) {
        float ts = 0.f, tss = 0.f;
        int nw = blockDim.x >> 5;
        for (int i = 0; i < nw; i++) { ts += rs[i]; tss += rss[i]; }
        rs[0] = ts; rss[0] = tss;
    }
    __syncthreads();
    float mu   = rs[0] / (float)CNT;
    float var  = rss[0] / (float)CNT - mu * mu;
    float rsig = rsqrtf(var + 1e-5f);

    for (int i = tid; i < CNT / 4; i += blockDim.x) {
        int c = g * CPG + (i >> 10);
        float sc = w[c] * rsig;
        float sh = b[c] - mu * sc;
        float4 v = x4[i];
        v.x = v.x * sc + sh;
        v.y = v.y * sc + sh;
        v.z = v.z * sc + sh;
        v.w = v.w * sc + sh;
        o4[i] = v;
    }
}

// ============================================================================
// Split-bf16 tensor-core GEMM.
//   C[m,n] = alpha * sum_k A(m,k)*B(k,n) (+bias[m]) (+res)
//   TA=false: A [M x K] (k contig)   TA=true: A [K x M] (m contig)
//   TB=false: B [K x N] (n contig)   TB=true: B [N x K] (k contig)
// BM=BN=128, BK=32, 256 threads (8 warps 2x4), warp tile 64x32.
// ============================================================================
template <bool TA, bool TB>
__global__ __launch_bounds__(256)
void mgemm_kernel(const float* __restrict__ A, const float* __restrict__ B,
                  float* __restrict__ C,
                  int M, int N, int K, int lda, int ldb, int ldc,
                  long long sA, long long sB, long long sC,
                  const float* __restrict__ bias,
                  const float* __restrict__ res, long long sRes,
                  float alpha)
{
    const int BM = 128, BN = 128, BK = 32;
    const int AST = TA ? (BM + 8) : (BK + 8);
    const int BST = TB ? (BK + 8) : (BN + 8);
    const int ASZ = TA ? (BK * AST) : (BM * AST);
    const int BSZ = TB ? (BN * BST) : (BK * BST);

    __shared__ __nv_bfloat16 Ah[ASZ];
    __shared__ __nv_bfloat16 Al[ASZ];
    __shared__ __nv_bfloat16 Bh[BSZ];
    __shared__ __nv_bfloat16 Bl[BSZ];

    int z = blockIdx.z;
    A += (long long)z * sA;
    B += (long long)z * sB;
    C += (long long)z * sC;
    if (res) res += (long long)z * sRes;

    int m0 = blockIdx.y * BM;
    int n0 = blockIdx.x * BN;
    int tid  = threadIdx.x;
    int lane = tid & 31;
    int wid  = tid >> 5;
    int m_w = (wid >> 2) * 64;
    int n_w = (wid & 3) * 32;

    int a_base, b_base;
    if (!TA) {
        a_base = (m_w + (lane & 15)) * AST + ((lane >> 4) * 8);
    } else {
        a_base = (((lane >> 4) & 1) * 8 + (lane & 7)) * AST
               + m_w + ((lane >> 3) & 1) * 8;
    }
    if (!TB) {
        b_base = (((lane >> 3) & 1) * 8 + (lane & 7)) * BST
               + n_w + ((lane >> 4) & 1) * 8;
    } else {
        b_base = (n_w + ((lane >> 4) & 1) * 8 + (lane & 7)) * BST
               + ((lane >> 3) & 1) * 8;
    }

    float c[4][4][4];
    #pragma unroll
    for (int i = 0; i < 4; i++) {
        #pragma unroll
        for (int j = 0; j < 4; j++) {
            #pragma unroll
            for (int t = 0; t < 4; t++) c[i][j][t] = 0.f;
        }
    }

    for (int k0 = 0; k0 < K; k0 += BK) {
        #pragma unroll
        for (int r = 0; r < 4; r++) {
            int i = tid + r * 256;
            u32 h0, h1, l0, l1;
            if (!TA) {
                int m  = i >> 3;
                int kq = (i & 7) * 4;
                float4 v = *(const float4*)&A[(size_t)(m0 + m) * lda + k0 + kq];
                split4(v, h0, h1, l0, l1);
                int o = m * AST + kq;
                *(u32*)&Ah[o] = h0;
                *(u32*)&Ah[o + 2] = h1;
                *(u32*)&Al[o] = l0;
                *(u32*)&Al[o + 2] = l1;
            } else {
                int k  = i >> 5;
                int mq = (i & 31) * 4;
                float4 v = *(const float4*)&A[(size_t)(k0 + k) * lda + m0 + mq];
                split4(v, h0, h1, l0, l1);
                int o = k * AST + mq;
                *(u32*)&Ah[o] = h0;
                *(u32*)&Ah[o + 2] = h1;
                *(u32*)&Al[o] = l0;
                *(u32*)&Al[o + 2] = l1;
            }
            if (!TB) {
                int k  = i >> 5;
                int nq = (i & 31) * 4;
                float4 v = *(const float4*)&B[(size_t)(k0 + k) * ldb + n0 + nq];
                split4(v, h0, h1, l0, l1);
                int o = k * BST + nq;
                *(u32*)&Bh[o] = h0;
                *(u32*)&Bh[o + 2] = h1;
                *(u32*)&Bl[o] = l0;
                *(u32*)&Bl[o + 2] = l1;
            } else {
                int n  = i >> 3;
                int kq = (i & 7) * 4;
                float4 v = *(const float4*)&B[(size_t)(n0 + n) * ldb + k0 + kq];
                split4(v, h0, h1, l0, l1);
                int o = n * BST + kq;
                *(u32*)&Bh[o] = h0;
                *(u32*)&Bh[o + 2] = h1;
                *(u32*)&Bl[o] = l0;
                *(u32*)&Bl[o + 2] = l1;
            }
        }
        __syncthreads();

        #pragma unroll
        for (int ks = 0; ks < 2; ks++) {
            int aoff = a_base + (TA ? ks * 16 * AST : ks * 16);
            int boff = b_base + (TB ? ks * 16 : ks * 16 * BST);

            u32 ah[4][4], al[4][4], bh[2][4], bl[2][4];
            #pragma unroll
            for (int mt = 0; mt < 4; mt++) {
                int o = aoff + (TA ? mt * 16 : mt * 16 * AST);
                if (TA) {
                    ldsm4t(ah[mt], saddr(&Ah[o]));
                    ldsm4t(al[mt], saddr(&Al[o]));
                } else {
                    ldsm4(ah[mt], saddr(&Ah[o]));
                    ldsm4(al[mt], saddr(&Al[o]));
                }
            }
            #pragma unroll
            for (int p = 0; p < 2; p++) {
                int o = boff + (TB ? p * 16 * BST : p * 16);
                if (TB) {
                    ldsm4(bh[p], saddr(&Bh[o]));
                    ldsm4(bl[p], saddr(&Bl[o]));
                } else {
                    ldsm4t(bh[p], saddr(&Bh[o]));
                    ldsm4t(bl[p], saddr(&Bl[o]));
                }
            }
            #pragma unroll
            for (int mt = 0; mt < 4; mt++) {
                #pragma unroll
                for (int nt = 0; nt < 4; nt++) {
                    int p = nt >> 1;
                    int q = (nt & 1) * 2;
                    mma_bf16(c[mt][nt], ah[mt], bh[p][q], bh[p][q + 1]);
                    mma_bf16(c[mt][nt], ah[mt], bl[p][q], bl[p][q + 1]);
                    mma_bf16(c[mt][nt], al[mt], bh[p][q], bh[p][q + 1]);
                }
            }
        }
        __syncthreads();
    }

    int g  = lane >> 2;
    int tq = lane & 3;
    #pragma unroll
    for (int mt = 0; mt < 4; mt++) {
        int mr0 = m0 + m_w + mt * 16 + g;
        int mr1 = mr0 + 8;
        float b0v = bias ? bias[mr0] : 0.f;
        float b1v = bias ? bias[mr1] : 0.f;
        #pragma unroll
        for (int nt = 0; nt < 4; nt++) {
            int nc = n0 + n_w + nt * 8 + tq * 2;
            size_t o0 = (size_t)mr0 * ldc + nc;
            size_t o1 = (size_t)mr1 * ldc + nc;
            float2 v0, v1;
            v0.x = c[mt][nt][0] * alpha + b0v;
            v0.y = c[mt][nt][1] * alpha + b0v;
            v1.x = c[mt][nt][2] * alpha + b1v;
            v1.y = c[mt][nt][3] * alpha + b1v;
            if (res) {
                float2 r0 = *(const float2*)&res[o0];
                float2 r1 = *(const float2*)&res[o1];
                v0.x += r0.x; v0.y += r0.y;
                v1.x += r1.x; v1.y += r1.y;
            }
            *(float2*)&C[o0] = v0;
            *(float2*)&C[o1] = v1;
        }
    }
}

// ============================================================================
// Row softmax over attn[b, i, :] (row length 4096). 256 threads/row.
// ============================================================================
__global__ void softmax_kernel(float* __restrict__ attn)
{
    size_t row = blockIdx.x;
    float4* p = (float4*)(attn + row * N_DIM);
    int tid = threadIdx.x;
    __shared__ float sh[8];

    float4 r[4];
    float mx = -1e30f;
    #pragma unroll
    for (int i = 0; i < 4; i++) {
        r[i] = p[tid + i * 256];
        mx = fmaxf(mx, fmaxf(fmaxf(r[i].x, r[i].y), fmaxf(r[i].z, r[i].w)));
    }
    #pragma unroll
    for (int o = 16; o; o >>= 1) mx = fmaxf(mx, __shfl_xor_sync(0xffffffffu, mx, o));
    if ((tid & 31) == 0) sh[tid >> 5] = mx;
    __syncthreads();
    if (tid == 0) {
        float t = sh[0];
        for (int i = 1; i < 8; i++) t = fmaxf(t, sh[i]);
        sh[0] = t;
    }
    __syncthreads();
    mx = sh[0];
    __syncthreads();

    float sum = 0.f;
    #pragma unroll
    for (int i = 0; i < 4; i++) {
        r[i].x = __expf(r[i].x - mx);
        r[i].y = __expf(r[i].y - mx);
        r[i].z = __expf(r[i].z - mx);
        r[i].w = __expf(r[i].w - mx);
        sum += r[i].x + r[i].y + r[i].z + r[i].w;
    }
    #pragma unroll
    for (int o = 16; o; o >>= 1) sum += __shfl_xor_sync(0xffffffffu, sum, o);
    if ((tid & 31) == 0) sh[tid >> 5] = sum;
    __syncthreads();
    if (tid == 0) {
        float t = 0.f;
        for (int i = 0; i < 8; i++) t += sh[i];
        sh[0] = t;
    }
    __syncthreads();
    float inv = 1.f / sh[0];

    #pragma unroll
    for (int i = 0; i < 4; i++) {
        r[i].x *= inv;
        r[i].y *= inv;
        r[i].z *= inv;
        r[i].w *= inv;
        p[tid + i * 256] = r[i];
    }
}

// ============================================================================
// Host launcher
// ============================================================================
extern "C" void kernel_launch(void* const* d_in, const int* in_sizes, int n_in,
                              void* d_out, int out_size)
{
    const float* x   = (const float*)d_in[0];
    const float* gnw = (const float*)d_in[1];
    const float* gnb = (const float*)d_in[2];
    const float* wq  = (const float*)d_in[3];
    const float* bq  = (const float*)d_in[4];
    const float* wk  = (const float*)d_in[5];
    const float* bk  = (const float*)d_in[6];
    const float* wv  = (const float*)d_in[7];
    const float* bv  = (const float*)d_in[8];
    const float* wp  = (const float*)d_in[9];
    const float* bp  = (const float*)d_in[10];
    float* out = (float*)d_out;

    int B = in_sizes[0] / (C_DIM * N_DIM);
    if (B < 1) B = 1;
    if (B > MAXB) B = MAXB;

    float* p_xn;
    float* p_q;
    float* p_k;
    float* p_v;
    float* p_o;
    float* p_attn;
    cudaGetSymbolAddress((void**)&p_xn,   g_xn);
    cudaGetSymbolAddress((void**)&p_q,    g_q);
    cudaGetSymbolAddress((void**)&p_k,    g_k);
    cudaGetSymbolAddress((void**)&p_v,    g_v);
    cudaGetSymbolAddress((void**)&p_o,    g_o);
    cudaGetSymbolAddress((void**)&p_attn, g_attn);

    const long long CN = (long long)C_DIM * N_DIM;
    const long long NN = (long long)N_DIM * N_DIM;
    const float scale = 1.0f / sqrtf((float)C_DIM);

    // 1) GroupNorm -> g_xn
    groupnorm_kernel<<<B * 32, 256>>>(x, gnw, gnb, p_xn);

    // 2) Q/K/V projections: W[512x512] @ xn[512x4096] per batch
    {
        dim3 grid(N_DIM / 128, C_DIM / 128, B);
        mgemm_kernel<false, false><<<grid, 256>>>(wq, p_xn, p_q,
            C_DIM, N_DIM, C_DIM, C_DIM, N_DIM, N_DIM,
            0, CN, CN, bq, (const float*)0, 0, 1.0f);
        mgemm_kernel<false, false><<<grid, 256>>>(wk, p_xn, p_k,
            C_DIM, N_DIM, C_DIM, C_DIM, N_DIM, N_DIM,
            0, CN, CN, bk, (const float*)0, 0, 1.0f);
        mgemm_kernel<false, false><<<grid, 256>>>(wv, p_xn, p_v,
            C_DIM, N_DIM, C_DIM, C_DIM, N_DIM, N_DIM,
            0, CN, CN, bv, (const float*)0, 0, 1.0f);
    }

    // 3) Scores: S[i,j] = scale * sum_c q[c,i] k[c,j]
    {
        dim3 grid(N_DIM / 128, N_DIM / 128, B);
        mgemm_kernel<true, false><<<grid, 256>>>(p_q, p_k, p_attn,
            N_DIM, N_DIM, C_DIM, N_DIM, N_DIM, N_DIM,
            CN, CN, NN, (const float*)0, (const float*)0, 0, scale);
    }

    // 4) Softmax over each row of attn
    softmax_kernel<<<B * N_DIM, 256>>>(p_attn);

    // 5) out[c,i] = sum_j v[c,j] * P[i,j]
    {
        dim3 grid(N_DIM / 128, C_DIM / 128, B);
        mgemm_kernel<false, true><<<grid, 256>>>(p_v, p_attn, p_o,
            C_DIM, N_DIM, N_DIM, N_DIM, N_DIM, N_DIM,
            CN, NN, CN, (const float*)0, (const float*)0, 0, 1.0f);
    }

    // 6) Projection + bias + residual -> d_out
    {
        dim3 grid(N_DIM / 128, C_DIM / 128, B);
        mgemm_kernel<false, false><<<grid, 256>>>(wp, p_o, out,
            C_DIM, N_DIM, C_DIM, C_DIM, N_DIM, N_DIM,
            0, CN, CN, bp, x, CN, 1.0f);
    }
}

// round 4
// speedup vs baseline: 2.3369x; 1.4443x over previous
#include <cuda_runtime.h>
#include <cuda_bf16.h>
#include <stdint.h>
#include <math.h>

typedef unsigned int u32;

#define C_DIM 512
#define N_DIM 4096
#define MAXB  4

// -------- scratch (__device__ globals) --------------------------------------
__device__ __nv_bfloat16 g_xh[MAXB * C_DIM * N_DIM];
__device__ __nv_bfloat16 g_xl[MAXB * C_DIM * N_DIM];
__device__ __nv_bfloat16 g_qh[MAXB * C_DIM * N_DIM];
__device__ __nv_bfloat16 g_ql[MAXB * C_DIM * N_DIM];
__device__ __nv_bfloat16 g_kh[MAXB * C_DIM * N_DIM];
__device__ __nv_bfloat16 g_kl[MAXB * C_DIM * N_DIM];
__device__ __nv_bfloat16 g_vh[MAXB * C_DIM * N_DIM];
__device__ __nv_bfloat16 g_vl[MAXB * C_DIM * N_DIM];
__device__ __nv_bfloat16 g_oh[MAXB * C_DIM * N_DIM];
__device__ __nv_bfloat16 g_ol[MAXB * C_DIM * N_DIM];
__device__ __nv_bfloat16 g_wh[4 * C_DIM * C_DIM];
__device__ __nv_bfloat16 g_wl[4 * C_DIM * C_DIM];
__device__ float         g_attn[MAXB * (size_t)N_DIM * N_DIM];   // 268 MB
__device__ __nv_bfloat16 g_ph[MAXB * (size_t)N_DIM * N_DIM];     // 134 MB
__device__ __nv_bfloat16 g_pl[MAXB * (size_t)N_DIM * N_DIM];     // 134 MB

// ============================================================================
// Helpers
// ============================================================================
__device__ __forceinline__ u32 pack_bf(__nv_bfloat16 x, __nv_bfloat16 y)
{
    __nv_bfloat162 t(x, y);
    return *(u32*)&t;
}

__device__ __forceinline__ void split_store2(__nv_bfloat16* Ch, __nv_bfloat16* Cl,
                                             size_t o, float x, float y)
{
    __nv_bfloat16 hx = __float2bfloat16(x);
    __nv_bfloat16 hy = __float2bfloat16(y);
    __nv_bfloat16 lx = __float2bfloat16(x - __bfloat162float(hx));
    __nv_bfloat16 ly = __float2bfloat16(y - __bfloat162float(hy));
    *(u32*)&Ch[o] = pack_bf(hx, hy);
    *(u32*)&Cl[o] = pack_bf(lx, ly);
}

__device__ __forceinline__ u32 saddr(const void* p)
{
    return (u32)__cvta_generic_to_shared(p);
}

__device__ __forceinline__ void cp16(u32 dst, const void* src)
{
    asm volatile("cp.async.cg.shared.global [%0], [%1], 16;\n" :: "r"(dst), "l"(src));
}
__device__ __forceinline__ void cp_commit()
{
    asm volatile("cp.async.commit_group;\n");
}
template <int NN_>
__device__ __forceinline__ void cp_wait()
{
    asm volatile("cp.async.wait_group %0;\n" :: "n"(NN_));
}

__device__ __forceinline__ void ldsm4(u32* r, u32 a)
{
    asm volatile("ldmatrix.sync.aligned.m8n8.x4.shared.b16 {%0,%1,%2,%3}, [%4];\n"
        : "=r"(r[0]), "=r"(r[1]), "=r"(r[2]), "=r"(r[3]) : "r"(a));
}
__device__ __forceinline__ void ldsm4t(u32* r, u32 a)
{
    asm volatile("ldmatrix.sync.aligned.m8n8.x4.trans.shared.b16 {%0,%1,%2,%3}, [%4];\n"
        : "=r"(r[0]), "=r"(r[1]), "=r"(r[2]), "=r"(r[3]) : "r"(a));
}
__device__ __forceinline__ void mma_bf16(float* c, const u32* a, u32 b0, u32 b1)
{
    asm volatile(
        "mma.sync.aligned.m16n8k16.row.col.f32.bf16.bf16.f32 "
        "{%0,%1,%2,%3}, {%4,%5,%6,%7}, {%8,%9}, {%0,%1,%2,%3};\n"
        : "+f"(c[0]), "+f"(c[1]), "+f"(c[2]), "+f"(c[3])
        : "r"(a[0]), "r"(a[1]), "r"(a[2]), "r"(a[3]), "r"(b0), "r"(b1));
}

// ============================================================================
// fp32 -> split bf16 (for weights)
// ============================================================================
__global__ void split_kernel(const float* __restrict__ in,
                             __nv_bfloat16* __restrict__ h,
                             __nv_bfloat16* __restrict__ l, int n4)
{
    int i = blockIdx.x * blockDim.x + threadIdx.x;
    if (i >= n4) return;
    float4 v = ((const float4*)in)[i];
    split_store2(h, l, (size_t)i * 4,     v.x, v.y);
    split_store2(h, l, (size_t)i * 4 + 2, v.z, v.w);
}

// ============================================================================
// GroupNorm: 32 groups, 16 ch/group, eps=1e-5; writes split bf16
// ============================================================================
__global__ void groupnorm_kernel(const float* __restrict__ x,
                                 const float* __restrict__ w,
                                 const float* __restrict__ b,
                                 __nv_bfloat16* __restrict__ oh,
                                 __nv_bfloat16* __restrict__ ol)
{
    const int CPG = 16;
    const int CNT = CPG * N_DIM;
    int bg = blockIdx.x;
    int g  = bg & 31;
    int bb = bg >> 5;
    size_t base = ((size_t)bb * C_DIM + (size_t)g * CPG) * N_DIM;
    const float4* x4 = (const float4*)(x + base);
    int tid = threadIdx.x;

    float s = 0.f, ss = 0.f;
    for (int i = tid; i < CNT / 4; i += blockDim.x) {
        float4 v = x4[i];
        s  += v.x + v.y + v.z + v.w;
        ss += v.x * v.x + v.y * v.y + v.z * v.z + v.w * v.w;
    }
    __shared__ float rs[8], rss[8];
    #pragma unroll
    for (int o = 16; o; o >>= 1) {
        s  += __shfl_xor_sync(0xffffffffu, s,  o);
        ss += __shfl_xor_sync(0xffffffffu, ss, o);
    }
    int wid = tid >> 5;
    int lid = tid & 31;
    if (lid == 0) { rs[wid] = s; rss[wid] = ss; }
    __syncthreads();
    if (tid == 0) {
        float ts = 0.f, tss = 0.f;
        int nw = blockDim.x >> 5;
        for (int i = 0; i < nw; i++) { ts += rs[i]; tss += rss[i]; }
        rs[0] = ts; rss[0] = tss;
    }
    __syncthreads();
    float mu   = rs[0] / (float)CNT;
    float var  = rss[0] / (float)CNT - mu * mu;
    float rsig = rsqrtf(var + 1e-5f);

    for (int i = tid; i < CNT / 4; i += blockDim.x) {
        int c = g * CPG + (i >> 10);
        float sc = w[c] * rsig;
        float sh = b[c] - mu * sc;
        float4 v = x4[i];
        float v0 = v.x * sc + sh;
        float v1 = v.y * sc + sh;
        float v2 = v.z * sc + sh;
        float v3 = v.w * sc + sh;
        size_t o = base + (size_t)i * 4;
        split_store2(oh, ol, o,     v0, v1);
        split_store2(oh, ol, o + 2, v2, v3);
    }
}

// ============================================================================
// Pipelined split-bf16 tensor-core GEMM (cp.async, 3 stages).
//   C[m,n] = alpha * sum_k A(m,k)*B(k,n) (+bias[m]) (+res)
//   TA=false: A [M x K] k-contig    TA=true: A [K x M] m-contig
//   TB=false: B [K x N] n-contig    TB=true: B [N x K] k-contig
//   SPLITOUT: write Ch/Cl bf16 pairs instead of Cf fp32
// BM=BN=128, BK=32, 256 threads (8 warps, 2x4), warp tile 64x32.
// ============================================================================
#define NSTAGE 3

template <bool TA, bool TB, bool SPLITOUT>
__global__ __launch_bounds__(256)
void pgemm_kernel(const __nv_bfloat16* __restrict__ Agh,
                  const __nv_bfloat16* __restrict__ Agl,
                  const __nv_bfloat16* __restrict__ Bgh,
                  const __nv_bfloat16* __restrict__ Bgl,
                  float* __restrict__ Cf,
                  __nv_bfloat16* __restrict__ Ch,
                  __nv_bfloat16* __restrict__ Cl,
                  int K, int lda, int ldb, int ldc,
                  long long sA, long long sB, long long sC,
                  const float* __restrict__ bias,
                  const float* __restrict__ res, long long sRes,
                  float alpha)
{
    const int BK = 32;
    const int AST = TA ? 136 : 40;
    const int BST = TB ? 40 : 136;
    const int ASZ = TA ? (BK * AST) : (128 * AST);
    const int BSZ = TB ? (128 * BST) : (BK * BST);
    const int STAGE = 2 * (ASZ + BSZ);

    extern __shared__ __align__(16) char smraw[];
    __nv_bfloat16* sm = (__nv_bfloat16*)smraw;

    int z = blockIdx.z;
    Agh += (long long)z * sA;
    Agl += (long long)z * sA;
    Bgh += (long long)z * sB;
    Bgl += (long long)z * sB;
    if (SPLITOUT) { Ch += (long long)z * sC; Cl += (long long)z * sC; }
    else          { Cf += (long long)z * sC; }
    if (res) res += (long long)z * sRes;

    int m0 = blockIdx.y * 128;
    int n0 = blockIdx.x * 128;
    int tid  = threadIdx.x;
    int lane = tid & 31;
    int wid  = tid >> 5;
    int m_w = (wid >> 2) * 64;
    int n_w = (wid & 3) * 32;

    int a_base, b_base;
    if (!TA) {
        a_base = (m_w + (lane & 15)) * AST + ((lane >> 4) * 8);
    } else {
        a_base = (((lane >> 4) & 1) * 8 + (lane & 7)) * AST
               + m_w + ((lane >> 3) & 1) * 8;
    }
    if (!TB) {
        b_base = (((lane >> 3) & 1) * 8 + (lane & 7)) * BST
               + n_w + ((lane >> 4) & 1) * 8;
    } else {
        b_base = (n_w + ((lane >> 4) & 1) * 8 + (lane & 7)) * BST
               + ((lane >> 3) & 1) * 8;
    }

    float c[4][4][4];
    #pragma unroll
    for (int i = 0; i < 4; i++) {
        #pragma unroll
        for (int j = 0; j < 4; j++) {
            #pragma unroll
            for (int t = 0; t < 4; t++) c[i][j][t] = 0.f;
        }
    }

    int KT = K / BK;

    auto load_stage = [&](int st, int k0) {
        __nv_bfloat16* sAh = sm + st * STAGE;
        __nv_bfloat16* sAl = sAh + ASZ;
        __nv_bfloat16* sBh = sAl + ASZ;
        __nv_bfloat16* sBl = sBh + BSZ;
        #pragma unroll
        for (int r = 0; r < 2; r++) {
            int i = tid + r * 256;
            if (!TA) {
                int m  = i >> 2;
                int kq = (i & 3) * 8;
                size_t go = (size_t)(m0 + m) * lda + k0 + kq;
                int    so = m * AST + kq;
                cp16(saddr(sAh + so), Agh + go);
                cp16(saddr(sAl + so), Agl + go);
            } else {
                int k  = i >> 4;
                int mq = (i & 15) * 8;
                size_t go = (size_t)(k0 + k) * lda + m0 + mq;
                int    so = k * AST + mq;
                cp16(saddr(sAh + so), Agh + go);
                cp16(saddr(sAl + so), Agl + go);
            }
            if (!TB) {
                int k  = i >> 4;
                int nq = (i & 15) * 8;
                size_t go = (size_t)(k0 + k) * ldb + n0 + nq;
                int    so = k * BST + nq;
                cp16(saddr(sBh + so), Bgh + go);
                cp16(saddr(sBl + so), Bgl + go);
            } else {
                int n  = i >> 2;
                int kq = (i & 3) * 8;
                size_t go = (size_t)(n0 + n) * ldb + k0 + kq;
                int    so = n * BST + kq;
                cp16(saddr(sBh + so), Bgh + go);
                cp16(saddr(sBl + so), Bgl + go);
            }
        }
    };

    // prologue: fill NSTAGE-1 stages
    #pragma unroll
    for (int s = 0; s < NSTAGE - 1; s++) {
        if (s < KT) load_stage(s, s * BK);
        cp_commit();
    }

    for (int kt = 0; kt < KT; kt++) {
        cp_wait<NSTAGE - 2>();
        __syncthreads();

        int pf = kt + NSTAGE - 1;
        if (pf < KT) load_stage(pf % NSTAGE, pf * BK);
        cp_commit();

        int st = kt % NSTAGE;
        const __nv_bfloat16* pAh = sm + st * STAGE;
        const __nv_bfloat16* pAl = pAh + ASZ;
        const __nv_bfloat16* pBh = pAl + ASZ;
        const __nv_bfloat16* pBl = pBh + BSZ;

        #pragma unroll
        for (int ks = 0; ks < 2; ks++) {
            int aoff = a_base + (TA ? ks * 16 * AST : ks * 16);
            int boff = b_base + (TB ? ks * 16 : ks * 16 * BST);

            u32 ah[4][4], al[4][4], bh[2][4], bl[2][4];
            #pragma unroll
            for (int mt = 0; mt < 4; mt++) {
                int o = aoff + (TA ? mt * 16 : mt * 16 * AST);
                if (TA) {
                    ldsm4t(ah[mt], saddr(pAh + o));
                    ldsm4t(al[mt], saddr(pAl + o));
                } else {
                    ldsm4(ah[mt], saddr(pAh + o));
                    ldsm4(al[mt], saddr(pAl + o));
                }
            }
            #pragma unroll
            for (int p = 0; p < 2; p++) {
                int o = boff + (TB ? p * 16 * BST : p * 16);
                if (TB) {
                    ldsm4(bh[p], saddr(pBh + o));
                    ldsm4(bl[p], saddr(pBl + o));
                } else {
                    ldsm4t(bh[p], saddr(pBh + o));
                    ldsm4t(bl[p], saddr(pBl + o));
                }
            }
            #pragma unroll
            for (int mt = 0; mt < 4; mt++) {
                #pragma unroll
                for (int nt = 0; nt < 4; nt++) {
                    int p = nt >> 1;
                    int q = (nt & 1) * 2;
                    mma_bf16(c[mt][nt], ah[mt], bh[p][q], bh[p][q + 1]);
                    mma_bf16(c[mt][nt], ah[mt], bl[p][q], bl[p][q + 1]);
                    mma_bf16(c[mt][nt], al[mt], bh[p][q], bh[p][q + 1]);
                }
            }
        }
        __syncthreads();
    }

    // ---- epilogue ----
    int g  = lane >> 2;
    int tq = lane & 3;
    #pragma unroll
    for (int mt = 0; mt < 4; mt++) {
        int mr0 = m0 + m_w + mt * 16 + g;
        int mr1 = mr0 + 8;
        float b0v = bias ? bias[mr0] : 0.f;
        float b1v = bias ? bias[mr1] : 0.f;
        #pragma unroll
        for (int nt = 0; nt < 4; nt++) {
            int nc = n0 + n_w + nt * 8 + tq * 2;
            size_t o0 = (size_t)mr0 * ldc + nc;
            size_t o1 = (size_t)mr1 * ldc + nc;
            float v00 = c[mt][nt][0] * alpha + b0v;
            float v01 = c[mt][nt][1] * alpha + b0v;
            float v10 = c[mt][nt][2] * alpha + b1v;
            float v11 = c[mt][nt][3] * alpha + b1v;
            if (SPLITOUT) {
                split_store2(Ch, Cl, o0, v00, v01);
                split_store2(Ch, Cl, o1, v10, v11);
            } else {
                if (res) {
                    float2 r0 = *(const float2*)&res[o0];
                    float2 r1 = *(const float2*)&res[o1];
                    v00 += r0.x; v01 += r0.y;
                    v10 += r1.x; v11 += r1.y;
                }
                float2 w0; w0.x = v00; w0.y = v01;
                float2 w1; w1.x = v10; w1.y = v11;
                *(float2*)&Cf[o0] = w0;
                *(float2*)&Cf[o1] = w1;
            }
        }
    }
}

// ============================================================================
// Row softmax over attn[b,i,:] (4096), writes split bf16 P.
// ============================================================================
__global__ void softmax_kernel(const float* __restrict__ attn,
                               __nv_bfloat16* __restrict__ ph,
                               __nv_bfloat16* __restrict__ pl)
{
    size_t row = blockIdx.x;
    const float4* p = (const float4*)(attn + row * N_DIM);
    int tid = threadIdx.x;
    __shared__ float sh[8];

    float4 r[4];
    float mx = -1e30f;
    #pragma unroll
    for (int i = 0; i < 4; i++) {
        r[i] = p[tid + i * 256];
        mx = fmaxf(mx, fmaxf(fmaxf(r[i].x, r[i].y), fmaxf(r[i].z, r[i].w)));
    }
    #pragma unroll
    for (int o = 16; o; o >>= 1) mx = fmaxf(mx, __shfl_xor_sync(0xffffffffu, mx, o));
    if ((tid & 31) == 0) sh[tid >> 5] = mx;
    __syncthreads();
    if (tid == 0) {
        float t = sh[0];
        for (int i = 1; i < 8; i++) t = fmaxf(t, sh[i]);
        sh[0] = t;
    }
    __syncthreads();
    mx = sh[0];
    __syncthreads();

    float sum = 0.f;
    #pragma unroll
    for (int i = 0; i < 4; i++) {
        r[i].x = __expf(r[i].x - mx);
        r[i].y = __expf(r[i].y - mx);
        r[i].z = __expf(r[i].z - mx);
        r[i].w = __expf(r[i].w - mx);
        sum += r[i].x + r[i].y + r[i].z + r[i].w;
    }
    #pragma unroll
    for (int o = 16; o; o >>= 1) sum += __shfl_xor_sync(0xffffffffu, sum, o);
    if ((tid & 31) == 0) sh[tid >> 5] = sum;
    __syncthreads();
    if (tid == 0) {
        float t = 0.f;
        for (int i = 0; i < 8; i++) t += sh[i];
        sh[0] = t;
    }
    __syncthreads();
    float inv = 1.f / sh[0];

    #pragma unroll
    for (int i = 0; i < 4; i++) {
        size_t o = row * N_DIM + (size_t)(tid + i * 256) * 4;
        split_store2(ph, pl, o,     r[i].x * inv, r[i].y * inv);
        split_store2(ph, pl, o + 2, r[i].z * inv, r[i].w * inv);
    }
}

// ============================================================================
// Host launcher
// ============================================================================
static int smem_stage_bytes(bool ta, bool tb)
{
    int AST = ta ? 136 : 40;
    int BST = tb ? 40 : 136;
    int ASZ = ta ? (32 * AST) : (128 * AST);
    int BSZ = tb ? (128 * BST) : (32 * BST);
    return 2 * (ASZ + BSZ) * 2;   // h+l arrays, 2 bytes/elem
}

extern "C" void kernel_launch(void* const* d_in, const int* in_sizes, int n_in,
                              void* d_out, int out_size)
{
    const float* x   = (const float*)d_in[0];
    const float* gnw = (const float*)d_in[1];
    const float* gnb = (const float*)d_in[2];
    const float* wq  = (const float*)d_in[3];
    const float* bq  = (const float*)d_in[4];
    const float* wk  = (const float*)d_in[5];
    const float* bk  = (const float*)d_in[6];
    const float* wv  = (const float*)d_in[7];
    const float* bv  = (const float*)d_in[8];
    const float* wp  = (const float*)d_in[9];
    const float* bp  = (const float*)d_in[10];
    float* out = (float*)d_out;

    int B = in_sizes[0] / (C_DIM * N_DIM);
    if (B < 1) B = 1;
    if (B > MAXB) B = MAXB;

    __nv_bfloat16 *xh, *xl, *qh, *ql, *kh, *kl, *vh, *vl, *oh, *ol;
    __nv_bfloat16 *wh, *wl, *ph, *pl;
    float* attn;
    cudaGetSymbolAddress((void**)&xh, g_xh);
    cudaGetSymbolAddress((void**)&xl, g_xl);
    cudaGetSymbolAddress((void**)&qh, g_qh);
    cudaGetSymbolAddress((void**)&ql, g_ql);
    cudaGetSymbolAddress((void**)&kh, g_kh);
    cudaGetSymbolAddress((void**)&kl, g_kl);
    cudaGetSymbolAddress((void**)&vh, g_vh);
    cudaGetSymbolAddress((void**)&vl, g_vl);
    cudaGetSymbolAddress((void**)&oh, g_oh);
    cudaGetSymbolAddress((void**)&ol, g_ol);
    cudaGetSymbolAddress((void**)&wh, g_wh);
    cudaGetSymbolAddress((void**)&wl, g_wl);
    cudaGetSymbolAddress((void**)&ph, g_ph);
    cudaGetSymbolAddress((void**)&pl, g_pl);
    cudaGetSymbolAddress((void**)&attn, g_attn);

    const long long CN = (long long)C_DIM * N_DIM;
    const long long NN = (long long)N_DIM * N_DIM;
    const long long CC = (long long)C_DIM * C_DIM;
    const float scale = 1.0f / sqrtf((float)C_DIM);

    int smem00 = NSTAGE * smem_stage_bytes(false, false);
    int smem10 = NSTAGE * smem_stage_bytes(true,  false);
    int smem01 = NSTAGE * smem_stage_bytes(false, true);
    cudaFuncSetAttribute(pgemm_kernel<false, false, true>,
                         cudaFuncAttributeMaxDynamicSharedMemorySize, smem00);
    cudaFuncSetAttribute(pgemm_kernel<false, false, false>,
                         cudaFuncAttributeMaxDynamicSharedMemorySize, smem00);
    cudaFuncSetAttribute(pgemm_kernel<true, false, false>,
                         cudaFuncAttributeMaxDynamicSharedMemorySize, smem10);
    cudaFuncSetAttribute(pgemm_kernel<false, true, true>,
                         cudaFuncAttributeMaxDynamicSharedMemorySize, smem01);

    // 1) GroupNorm -> split xn
    groupnorm_kernel<<<B * 32, 256>>>(x, gnw, gnb, xh, xl);

    // 2) Split the 4 weight matrices
    {
        int n4 = C_DIM * C_DIM / 4;
        int tb = 256, gb = (n4 + tb - 1) / tb;
        split_kernel<<<gb, tb>>>(wq, wh + 0 * CC, wl + 0 * CC, n4);
        split_kernel<<<gb, tb>>>(wk, wh + 1 * CC, wl + 1 * CC, n4);
        split_kernel<<<gb, tb>>>(wv, wh + 2 * CC, wl + 2 * CC, n4);
        split_kernel<<<gb, tb>>>(wp, wh + 3 * CC, wl + 3 * CC, n4);
    }

    // 3) Q/K/V projections (split-out)
    {
        dim3 grid(N_DIM / 128, C_DIM / 128, B);
        pgemm_kernel<false, false, true><<<grid, 256, smem00>>>(
            wh + 0 * CC, wl + 0 * CC, xh, xl, (float*)0, qh, ql,
            C_DIM, C_DIM, N_DIM, N_DIM, 0, CN, CN, bq, (const float*)0, 0, 1.0f);
        pgemm_kernel<false, false, true><<<grid, 256, smem00>>>(
            wh + 1 * CC, wl + 1 * CC, xh, xl, (float*)0, kh, kl,
            C_DIM, C_DIM, N_DIM, N_DIM, 0, CN, CN, bk, (const float*)0, 0, 1.0f);
        pgemm_kernel<false, false, true><<<grid, 256, smem00>>>(
            wh + 2 * CC, wl + 2 * CC, xh, xl, (float*)0, vh, vl,
            C_DIM, C_DIM, N_DIM, N_DIM, 0, CN, CN, bv, (const float*)0, 0, 1.0f);
    }

    // 4) Scores: S[i,j] = scale * sum_c q[c,i] k[c,j]  (fp32 out)
    {
        dim3 grid(N_DIM / 128, N_DIM / 128, B);
        pgemm_kernel<true, false, false><<<grid, 256, smem10>>>(
            qh, ql, kh, kl, attn, (__nv_bfloat16*)0, (__nv_bfloat16*)0,
            C_DIM, N_DIM, N_DIM, N_DIM, CN, CN, NN,
            (const float*)0, (const float*)0, 0, scale);
    }

    // 5) Softmax -> split P
    softmax_kernel<<<B * N_DIM, 256>>>(attn, ph, pl);

    // 6) out[c,i] = sum_j v[c,j] * P[i,j]  (split-out)
    {
        dim3 grid(N_DIM / 128, C_DIM / 128, B);
        pgemm_kernel<false, true, true><<<grid, 256, smem01>>>(
            vh, vl, ph, pl, (float*)0, oh, ol,
            N_DIM, N_DIM, N_DIM, N_DIM, CN, NN, CN,
            (const float*)0, (const float*)0, 0, 1.0f);
    }

    // 7) Projection + bias + residual -> d_out (fp32)
    {
        dim3 grid(N_DIM / 128, C_DIM / 128, B);
        pgemm_kernel<false, false, false><<<grid, 256, smem00>>>(
            wh + 3 * CC, wl + 3 * CC, oh, ol, out,
            (__nv_bfloat16*)0, (__nv_bfloat16*)0,
            C_DIM, C_DIM, N_DIM, N_DIM, 0, CN, CN, bp, x, CN, 1.0f);
    }
}

// round 7
// speedup vs baseline: 2.5528x; 1.0924x over previous
#include <cuda_runtime.h>
#include <cuda_bf16.h>
#include <stdint.h>
#include <math.h>

typedef unsigned int u32;

#define C_DIM 512
#define N_DIM 4096
#define MAXB  4

// -------- scratch (__device__ globals) --------------------------------------
__device__ __nv_bfloat16 g_xh[MAXB * C_DIM * N_DIM];
__device__ __nv_bfloat16 g_xl[MAXB * C_DIM * N_DIM];
__device__ __nv_bfloat16 g_qh[MAXB * C_DIM * N_DIM];
__device__ __nv_bfloat16 g_ql[MAXB * C_DIM * N_DIM];
__device__ __nv_bfloat16 g_kh[MAXB * C_DIM * N_DIM];
__device__ __nv_bfloat16 g_kl[MAXB * C_DIM * N_DIM];
__device__ __nv_bfloat16 g_vh[MAXB * C_DIM * N_DIM];
__device__ __nv_bfloat16 g_vl[MAXB * C_DIM * N_DIM];
__device__ __nv_bfloat16 g_oh[MAXB * C_DIM * N_DIM];
__device__ __nv_bfloat16 g_ol[MAXB * C_DIM * N_DIM];
__device__ __nv_bfloat16 g_wh[4 * C_DIM * C_DIM];
__device__ __nv_bfloat16 g_wl[4 * C_DIM * C_DIM];
__device__ float         g_attn[MAXB * (size_t)N_DIM * N_DIM];   // 268 MB
__device__ __nv_bfloat16 g_ph[MAXB * (size_t)N_DIM * N_DIM];     // 134 MB
__device__ __nv_bfloat16 g_pl[MAXB * (size_t)N_DIM * N_DIM];     // 134 MB

// ============================================================================
// Helpers
// ============================================================================
__device__ __forceinline__ u32 pack_bf(__nv_bfloat16 x, __nv_bfloat16 y)
{
    __nv_bfloat162 t(x, y);
    return *(u32*)&t;
}

__device__ __forceinline__ void split_store2(__nv_bfloat16* Ch, __nv_bfloat16* Cl,
                                             size_t o, float x, float y)
{
    __nv_bfloat16 hx = __float2bfloat16(x);
    __nv_bfloat16 hy = __float2bfloat16(y);
    __nv_bfloat16 lx = __float2bfloat16(x - __bfloat162float(hx));
    __nv_bfloat16 ly = __float2bfloat16(y - __bfloat162float(hy));
    *(u32*)&Ch[o] = pack_bf(hx, hy);
    *(u32*)&Cl[o] = pack_bf(lx, ly);
}

__device__ __forceinline__ u32 saddr(const void* p)
{
    return (u32)__cvta_generic_to_shared(p);
}

__device__ __forceinline__ void cp16(u32 dst, const void* src)
{
    asm volatile("cp.async.cg.shared.global [%0], [%1], 16;\n" :: "r"(dst), "l"(src));
}
__device__ __forceinline__ void cp_commit()
{
    asm volatile("cp.async.commit_group;\n");
}
template <int NN_>
__device__ __forceinline__ void cp_wait()
{
    asm volatile("cp.async.wait_group %0;\n" :: "n"(NN_));
}

__device__ __forceinline__ void ldsm4(u32* r, u32 a)
{
    asm volatile("ldmatrix.sync.aligned.m8n8.x4.shared.b16 {%0,%1,%2,%3}, [%4];\n"
        : "=r"(r[0]), "=r"(r[1]), "=r"(r[2]), "=r"(r[3]) : "r"(a));
}
__device__ __forceinline__ void ldsm4t(u32* r, u32 a)
{
    asm volatile("ldmatrix.sync.aligned.m8n8.x4.trans.shared.b16 {%0,%1,%2,%3}, [%4];\n"
        : "=r"(r[0]), "=r"(r[1]), "=r"(r[2]), "=r"(r[3]) : "r"(a));
}
__device__ __forceinline__ void mma_bf16(float* c, const u32* a, u32 b0, u32 b1)
{
    asm volatile(
        "mma.sync.aligned.m16n8k16.row.col.f32.bf16.bf16.f32 "
        "{%0,%1,%2,%3}, {%4,%5,%6,%7}, {%8,%9}, {%0,%1,%2,%3};\n"
        : "+f"(c[0]), "+f"(c[1]), "+f"(c[2]), "+f"(c[3])
        : "r"(a[0]), "r"(a[1]), "r"(a[2]), "r"(a[3]), "r"(b0), "r"(b1));
}

// ============================================================================
// fp32 -> split bf16 (for weights)
// ============================================================================
__global__ void split_kernel(const float* __restrict__ in,
                             __nv_bfloat16* __restrict__ h,
                             __nv_bfloat16* __restrict__ l, int n4)
{
    int i = blockIdx.x * blockDim.x + threadIdx.x;
    if (i >= n4) return;
    float4 v = ((const float4*)in)[i];
    split_store2(h, l, (size_t)i * 4,     v.x, v.y);
    split_store2(h, l, (size_t)i * 4 + 2, v.z, v.w);
}

// ============================================================================
// GroupNorm: 32 groups, 16 ch/group, eps=1e-5; writes split bf16
// ============================================================================
__global__ void groupnorm_kernel(const float* __restrict__ x,
                                 const float* __restrict__ w,
                                 const float* __restrict__ b,
                                 __nv_bfloat16* __restrict__ oh,
                                 __nv_bfloat16* __restrict__ ol)
{
    const int CPG = 16;
    const int CNT = CPG * N_DIM;
    int bg = blockIdx.x;
    int g  = bg & 31;
    int bb = bg >> 5;
    size_t base = ((size_t)bb * C_DIM + (size_t)g * CPG) * N_DIM;
    const float4* x4 = (const float4*)(x + base);
    int tid = threadIdx.x;

    float s = 0.f, ss = 0.f;
    for (int i = tid; i < CNT / 4; i += blockDim.x) {
        float4 v = x4[i];
        s  += v.x + v.y + v.z + v.w;
        ss += v.x * v.x + v.y * v.y + v.z * v.z + v.w * v.w;
    }
    __shared__ float rs[8], rss[8];
    #pragma unroll
    for (int o = 16; o; o >>= 1) {
        s  += __shfl_xor_sync(0xffffffffu, s,  o);
        ss += __shfl_xor_sync(0xffffffffu, ss, o);
    }
    int wid = tid >> 5;
    int lid = tid & 31;
    if (lid == 0) { rs[wid] = s; rss[wid] = ss; }
    __syncthreads();
    if (tid == 0) {
        float ts = 0.f, tss = 0.f;
        int nw = blockDim.x >> 5;
        for (int i = 0; i < nw; i++) { ts += rs[i]; tss += rss[i]; }
        rs[0] = ts; rss[0] = tss;
    }
    __syncthreads();
    float mu   = rs[0] / (float)CNT;
    float var  = rss[0] / (float)CNT - mu * mu;
    float rsig = rsqrtf(var + 1e-5f);

    for (int i = tid; i < CNT / 4; i += blockDim.x) {
        int c = g * CPG + (i >> 10);
        float sc = w[c] * rsig;
        float sh = b[c] - mu * sc;
        float4 v = x4[i];
        float v0 = v.x * sc + sh;
        float v1 = v.y * sc + sh;
        float v2 = v.z * sc + sh;
        float v3 = v.w * sc + sh;
        size_t o = base + (size_t)i * 4;
        split_store2(oh, ol, o,     v0, v1);
        split_store2(oh, ol, o + 2, v2, v3);
    }
}

// ============================================================================
// Pipelined split-bf16 tensor-core GEMM (cp.async, 2 stages, 2 CTAs/SM).
//   C[m,n] = alpha * sum_k A(m,k)*B(k,n) (+bias[m]) (+res)
//   TA=false: A [M x K] k-contig    TA=true: A [K x M] m-contig
//   TB=false: B [K x N] n-contig    TB=true: B [N x K] k-contig
//   SPLITOUT: write Ch/Cl bf16 pairs instead of Cf fp32
// BM=BN=128, BK=32, 256 threads (8 warps, 2x4), warp tile 64x32.
// ============================================================================
#define NSTAGE 2

template <bool TA, bool TB, bool SPLITOUT>
__global__ __launch_bounds__(256, 2)
void pgemm_kernel(const __nv_bfloat16* __restrict__ Agh,
                  const __nv_bfloat16* __restrict__ Agl,
                  const __nv_bfloat16* __restrict__ Bgh,
                  const __nv_bfloat16* __restrict__ Bgl,
                  float* __restrict__ Cf,
                  __nv_bfloat16* __restrict__ Ch,
                  __nv_bfloat16* __restrict__ Cl,
                  int K, int lda, int ldb, int ldc,
                  long long sA, long long sB, long long sC,
                  const float* __restrict__ bias,
                  const float* __restrict__ res, long long sRes,
                  float alpha)
{
    const int BK = 32;
    const int AST = TA ? 136 : 40;
    const int BST = TB ? 40 : 136;
    const int ASZ = TA ? (BK * AST) : (128 * AST);
    const int BSZ = TB ? (128 * BST) : (BK * BST);
    const int STAGE = 2 * (ASZ + BSZ);

    extern __shared__ __align__(16) char smraw[];
    __nv_bfloat16* sm = (__nv_bfloat16*)smraw;

    int z = blockIdx.z;
    Agh += (long long)z * sA;
    Agl += (long long)z * sA;
    Bgh += (long long)z * sB;
    Bgl += (long long)z * sB;
    if (SPLITOUT) { Ch += (long long)z * sC; Cl += (long long)z * sC; }
    else          { Cf += (long long)z * sC; }
    if (res) res += (long long)z * sRes;

    int m0 = blockIdx.y * 128;
    int n0 = blockIdx.x * 128;
    int tid  = threadIdx.x;
    int lane = tid & 31;
    int wid  = tid >> 5;
    int m_w = (wid >> 2) * 64;
    int n_w = (wid & 3) * 32;

    int a_base, b_base;
    if (!TA) {
        a_base = (m_w + (lane & 15)) * AST + ((lane >> 4) * 8);
    } else {
        a_base = (((lane >> 4) & 1) * 8 + (lane & 7)) * AST
               + m_w + ((lane >> 3) & 1) * 8;
    }
    if (!TB) {
        b_base = (((lane >> 3) & 1) * 8 + (lane & 7)) * BST
               + n_w + ((lane >> 4) & 1) * 8;
    } else {
        b_base = (n_w + ((lane >> 4) & 1) * 8 + (lane & 7)) * BST
               + ((lane >> 3) & 1) * 8;
    }

    float c[4][4][4];
    #pragma unroll
    for (int i = 0; i < 4; i++) {
        #pragma unroll
        for (int j = 0; j < 4; j++) {
            #pragma unroll
            for (int t = 0; t < 4; t++) c[i][j][t] = 0.f;
        }
    }

    int KT = K / BK;

    auto load_stage = [&](int st, int k0) {
        __nv_bfloat16* sAh = sm + st * STAGE;
        __nv_bfloat16* sAl = sAh + ASZ;
        __nv_bfloat16* sBh = sAl + ASZ;
        __nv_bfloat16* sBl = sBh + BSZ;
        #pragma unroll
        for (int r = 0; r < 2; r++) {
            int i = tid + r * 256;
            if (!TA) {
                int m  = i >> 2;
                int kq = (i & 3) * 8;
                size_t go = (size_t)(m0 + m) * lda + k0 + kq;
                int    so = m * AST + kq;
                cp16(saddr(sAh + so), Agh + go);
                cp16(saddr(sAl + so), Agl + go);
            } else {
                int k  = i >> 4;
                int mq = (i & 15) * 8;
                size_t go = (size_t)(k0 + k) * lda + m0 + mq;
                int    so = k * AST + mq;
                cp16(saddr(sAh + so), Agh + go);
                cp16(saddr(sAl + so), Agl + go);
            }
            if (!TB) {
                int k  = i >> 4;
                int nq = (i & 15) * 8;
                size_t go = (size_t)(k0 + k) * ldb + n0 + nq;
                int    so = k * BST + nq;
                cp16(saddr(sBh + so), Bgh + go);
                cp16(saddr(sBl + so), Bgl + go);
            } else {
                int n  = i >> 2;
                int kq = (i & 3) * 8;
                size_t go = (size_t)(n0 + n) * ldb + k0 + kq;
                int    so = n * BST + kq;
                cp16(saddr(sBh + so), Bgh + go);
                cp16(saddr(sBl + so), Bgl + go);
            }
        }
    };

    // prologue: fill NSTAGE-1 stages
    #pragma unroll
    for (int s = 0; s < NSTAGE - 1; s++) {
        if (s < KT) load_stage(s, s * BK);
        cp_commit();
    }

    for (int kt = 0; kt < KT; kt++) {
        cp_wait<NSTAGE - 2>();
        __syncthreads();

        int pf = kt + NSTAGE - 1;
        if (pf < KT) load_stage(pf % NSTAGE, pf * BK);
        cp_commit();

        int st = kt % NSTAGE;
        const __nv_bfloat16* pAh = sm + st * STAGE;
        const __nv_bfloat16* pAl = pAh + ASZ;
        const __nv_bfloat16* pBh = pAl + ASZ;
        const __nv_bfloat16* pBl = pBh + BSZ;

        #pragma unroll
        for (int ks = 0; ks < 2; ks++) {
            int aoff = a_base + (TA ? ks * 16 * AST : ks * 16);
            int boff = b_base + (TB ? ks * 16 : ks * 16 * BST);

            u32 ah[4][4], al[4][4], bh[2][4], bl[2][4];
            #pragma unroll
            for (int mt = 0; mt < 4; mt++) {
                int o = aoff + (TA ? mt * 16 : mt * 16 * AST);
                if (TA) {
                    ldsm4t(ah[mt], saddr(pAh + o));
                    ldsm4t(al[mt], saddr(pAl + o));
                } else {
                    ldsm4(ah[mt], saddr(pAh + o));
                    ldsm4(al[mt], saddr(pAl + o));
                }
            }
            #pragma unroll
            for (int p = 0; p < 2; p++) {
                int o = boff + (TB ? p * 16 * BST : p * 16);
                if (TB) {
                    ldsm4(bh[p], saddr(pBh + o));
                    ldsm4(bl[p], saddr(pBl + o));
                } else {
                    ldsm4t(bh[p], saddr(pBh + o));
                    ldsm4t(bl[p], saddr(pBl + o));
                }
            }
            #pragma unroll
            for (int mt = 0; mt < 4; mt++) {
                #pragma unroll
                for (int nt = 0; nt < 4; nt++) {
                    int p = nt >> 1;
                    int q = (nt & 1) * 2;
                    mma_bf16(c[mt][nt], ah[mt], bh[p][q], bh[p][q + 1]);
                    mma_bf16(c[mt][nt], ah[mt], bl[p][q], bl[p][q + 1]);
                    mma_bf16(c[mt][nt], al[mt], bh[p][q], bh[p][q + 1]);
                }
            }
        }
        __syncthreads();
    }

    // ---- epilogue ----
    int g  = lane >> 2;
    int tq = lane & 3;
    #pragma unroll
    for (int mt = 0; mt < 4; mt++) {
        int mr0 = m0 + m_w + mt * 16 + g;
        int mr1 = mr0 + 8;
        float b0v = bias ? bias[mr0] : 0.f;
        float b1v = bias ? bias[mr1] : 0.f;
        #pragma unroll
        for (int nt = 0; nt < 4; nt++) {
            int nc = n0 + n_w + nt * 8 + tq * 2;
            size_t o0 = (size_t)mr0 * ldc + nc;
            size_t o1 = (size_t)mr1 * ldc + nc;
            float v00 = c[mt][nt][0] * alpha + b0v;
            float v01 = c[mt][nt][1] * alpha + b0v;
            float v10 = c[mt][nt][2] * alpha + b1v;
            float v11 = c[mt][nt][3] * alpha + b1v;
            if (SPLITOUT) {
                split_store2(Ch, Cl, o0, v00, v01);
                split_store2(Ch, Cl, o1, v10, v11);
            } else {
                if (res) {
                    float2 r0 = *(const float2*)&res[o0];
                    float2 r1 = *(const float2*)&res[o1];
                    v00 += r0.x; v01 += r0.y;
                    v10 += r1.x; v11 += r1.y;
                }
                float2 w0; w0.x = v00; w0.y = v01;
                float2 w1; w1.x = v10; w1.y = v11;
                *(float2*)&Cf[o0] = w0;
                *(float2*)&Cf[o1] = w1;
            }
        }
    }
}

// ============================================================================
// Row softmax over attn[b,i,:] (4096), writes split bf16 P.
// ============================================================================
__global__ void softmax_kernel(const float* __restrict__ attn,
                               __nv_bfloat16* __restrict__ ph,
                               __nv_bfloat16* __restrict__ pl)
{
    size_t row = blockIdx.x;
    const float4* p = (const float4*)(attn + row * N_DIM);
    int tid = threadIdx.x;
    __shared__ float sh[8];

    float4 r[4];
    float mx = -1e30f;
    #pragma unroll
    for (int i = 0; i < 4; i++) {
        r[i] = p[tid + i * 256];
        mx = fmaxf(mx, fmaxf(fmaxf(r[i].x, r[i].y), fmaxf(r[i].z, r[i].w)));
    }
    #pragma unroll
    for (int o = 16; o; o >>= 1) mx = fmaxf(mx, __shfl_xor_sync(0xffffffffu, mx, o));
    if ((tid & 31) == 0) sh[tid >> 5] = mx;
    __syncthreads();
    if (tid == 0) {
        float t = sh[0];
        for (int i = 1; i < 8; i++) t = fmaxf(t, sh[i]);
        sh[0] = t;
    }
    __syncthreads();
    mx = sh[0];
    __syncthreads();

    float sum = 0.f;
    #pragma unroll
    for (int i = 0; i < 4; i++) {
        r[i].x = __expf(r[i].x - mx);
        r[i].y = __expf(r[i].y - mx);
        r[i].z = __expf(r[i].z - mx);
        r[i].w = __expf(r[i].w - mx);
        sum += r[i].x + r[i].y + r[i].z + r[i].w;
    }
    #pragma unroll
    for (int o = 16; o; o >>= 1) sum += __shfl_xor_sync(0xffffffffu, sum, o);
    if ((tid & 31) == 0) sh[tid >> 5] = sum;
    __syncthreads();
    if (tid == 0) {
        float t = 0.f;
        for (int i = 0; i < 8; i++) t += sh[i];
        sh[0] = t;
    }
    __syncthreads();
    float inv = 1.f / sh[0];

    #pragma unroll
    for (int i = 0; i < 4; i++) {
        size_t o = row * N_DIM + (size_t)(tid + i * 256) * 4;
        split_store2(ph, pl, o,     r[i].x * inv, r[i].y * inv);
        split_store2(ph, pl, o + 2, r[i].z * inv, r[i].w * inv);
    }
}

// ============================================================================
// Host launcher
// ============================================================================
static int smem_stage_bytes(bool ta, bool tb)
{
    int AST = ta ? 136 : 40;
    int BST = tb ? 40 : 136;
    int ASZ = ta ? (32 * AST) : (128 * AST);
    int BSZ = tb ? (128 * BST) : (32 * BST);
    return 2 * (ASZ + BSZ) * 2;   // h+l arrays, 2 bytes/elem
}

extern "C" void kernel_launch(void* const* d_in, const int* in_sizes, int n_in,
                              void* d_out, int out_size)
{
    const float* x   = (const float*)d_in[0];
    const float* gnw = (const float*)d_in[1];
    const float* gnb = (const float*)d_in[2];
    const float* wq  = (const float*)d_in[3];
    const float* bq  = (const float*)d_in[4];
    const float* wk  = (const float*)d_in[5];
    const float* bk  = (const float*)d_in[6];
    const float* wv  = (const float*)d_in[7];
    const float* bv  = (const float*)d_in[8];
    const float* wp  = (const float*)d_in[9];
    const float* bp  = (const float*)d_in[10];
    float* out = (float*)d_out;

    int B = in_sizes[0] / (C_DIM * N_DIM);
    if (B < 1) B = 1;
    if (B > MAXB) B = MAXB;

    __nv_bfloat16 *xh, *xl, *qh, *ql, *kh, *kl, *vh, *vl, *oh, *ol;
    __nv_bfloat16 *wh, *wl, *ph, *pl;
    float* attn;
    cudaGetSymbolAddress((void**)&xh, g_xh);
    cudaGetSymbolAddress((void**)&xl, g_xl);
    cudaGetSymbolAddress((void**)&qh, g_qh);
    cudaGetSymbolAddress((void**)&ql, g_ql);
    cudaGetSymbolAddress((void**)&kh, g_kh);
    cudaGetSymbolAddress((void**)&kl, g_kl);
    cudaGetSymbolAddress((void**)&vh, g_vh);
    cudaGetSymbolAddress((void**)&vl, g_vl);
    cudaGetSymbolAddress((void**)&oh, g_oh);
    cudaGetSymbolAddress((void**)&ol, g_ol);
    cudaGetSymbolAddress((void**)&wh, g_wh);
    cudaGetSymbolAddress((void**)&wl, g_wl);
    cudaGetSymbolAddress((void**)&ph, g_ph);
    cudaGetSymbolAddress((void**)&pl, g_pl);
    cudaGetSymbolAddress((void**)&attn, g_attn);

    const long long CN = (long long)C_DIM * N_DIM;
    const long long NN = (long long)N_DIM * N_DIM;
    const long long CC = (long long)C_DIM * C_DIM;
    const float scale = 1.0f / sqrtf((float)C_DIM);

    int smem00 = NSTAGE * smem_stage_bytes(false, false);
    int smem10 = NSTAGE * smem_stage_bytes(true,  false);
    int smem01 = NSTAGE * smem_stage_bytes(false, true);
    cudaFuncSetAttribute(pgemm_kernel<false, false, true>,
                         cudaFuncAttributeMaxDynamicSharedMemorySize, smem00);
    cudaFuncSetAttribute(pgemm_kernel<false, false, false>,
                         cudaFuncAttributeMaxDynamicSharedMemorySize, smem00);
    cudaFuncSetAttribute(pgemm_kernel<true, false, false>,
                         cudaFuncAttributeMaxDynamicSharedMemorySize, smem10);
    cudaFuncSetAttribute(pgemm_kernel<false, true, true>,
                         cudaFuncAttributeMaxDynamicSharedMemorySize, smem01);

    // 1) GroupNorm -> split xn
    groupnorm_kernel<<<B * 32, 256>>>(x, gnw, gnb, xh, xl);

    // 2) Split the 4 weight matrices
    {
        int n4 = C_DIM * C_DIM / 4;
        int tb = 256, gb = (n4 + tb - 1) / tb;
        split_kernel<<<gb, tb>>>(wq, wh + 0 * CC, wl + 0 * CC, n4);
        split_kernel<<<gb, tb>>>(wk, wh + 1 * CC, wl + 1 * CC, n4);
        split_kernel<<<gb, tb>>>(wv, wh + 2 * CC, wl + 2 * CC, n4);
        split_kernel<<<gb, tb>>>(wp, wh + 3 * CC, wl + 3 * CC, n4);
    }

    // 3) Q/K/V projections (split-out)
    {
        dim3 grid(N_DIM / 128, C_DIM / 128, B);
        pgemm_kernel<false, false, true><<<grid, 256, smem00>>>(
            wh + 0 * CC, wl + 0 * CC, xh, xl, (float*)0, qh, ql,
            C_DIM, C_DIM, N_DIM, N_DIM, 0, CN, CN, bq, (const float*)0, 0, 1.0f);
        pgemm_kernel<false, false, true><<<grid, 256, smem00>>>(
            wh + 1 * CC, wl + 1 * CC, xh, xl, (float*)0, kh, kl,
            C_DIM, C_DIM, N_DIM, N_DIM, 0, CN, CN, bk, (const float*)0, 0, 1.0f);
        pgemm_kernel<false, false, true><<<grid, 256, smem00>>>(
            wh + 2 * CC, wl + 2 * CC, xh, xl, (float*)0, vh, vl,
            C_DIM, C_DIM, N_DIM, N_DIM, 0, CN, CN, bv, (const float*)0, 0, 1.0f);
    }

    // 4) Scores: S[i,j] = scale * sum_c q[c,i] k[c,j]  (fp32 out)
    {
        dim3 grid(N_DIM / 128, N_DIM / 128, B);
        pgemm_kernel<true, false, false><<<grid, 256, smem10>>>(
            qh, ql, kh, kl, attn, (__nv_bfloat16*)0, (__nv_bfloat16*)0,
            C_DIM, N_DIM, N_DIM, N_DIM, CN, CN, NN,
            (const float*)0, (const float*)0, 0, scale);
    }

    // 5) Softmax -> split P
    softmax_kernel<<<B * N_DIM, 256>>>(attn, ph, pl);

    // 6) out[c,i] = sum_j v[c,j] * P[i,j]  (split-out)
    {
        dim3 grid(N_DIM / 128, C_DIM / 128, B);
        pgemm_kernel<false, true, true><<<grid, 256, smem01>>>(
            vh, vl, ph, pl, (float*)0, oh, ol,
            N_DIM, N_DIM, N_DIM, N_DIM, CN, NN, CN,
            (const float*)0, (const float*)0, 0, 1.0f);
    }

    // 7) Projection + bias + residual -> d_out (fp32)
    {
        dim3 grid(N_DIM / 128, C_DIM / 128, B);
        pgemm_kernel<false, false, false><<<grid, 256, smem00>>>(
            wh + 3 * CC, wl + 3 * CC, oh, ol, out,
            (__nv_bfloat16*)0, (__nv_bfloat16*)0,
            C_DIM, C_DIM, N_DIM, N_DIM, 0, CN, CN, bp, x, CN, 1.0f);
    }
}

// round 8
// speedup vs baseline: 3.3447x; 1.3102x over previous
#include <cuda_runtime.h>
#include <cuda_fp16.h>
#include <stdint.h>
#include <math.h>

typedef unsigned int u32;

#define C_DIM 512
#define N_DIM 4096
#define MAXB  4

// -------- scratch (__device__ globals) --------------------------------------
__device__ __half g_xh[MAXB * C_DIM * N_DIM];   // xn hi
__device__ __half g_xl[MAXB * C_DIM * N_DIM];   // xn lo
__device__ __half g_qh[MAXB * C_DIM * N_DIM];   // q hi
__device__ __half g_ql[MAXB * C_DIM * N_DIM];   // q lo
__device__ __half g_ks[MAXB * C_DIM * N_DIM];   // k single fp16
__device__ __half g_vh[MAXB * C_DIM * N_DIM];   // v hi
__device__ __half g_vl[MAXB * C_DIM * N_DIM];   // v lo
__device__ __half g_oh[MAXB * C_DIM * N_DIM];   // attn-out hi
__device__ __half g_ol[MAXB * C_DIM * N_DIM];   // attn-out lo
__device__ __half g_wh[4 * C_DIM * C_DIM];      // weights hi (q,k,v,p stacked)
__device__ __half g_wl[4 * C_DIM * C_DIM];      // weights lo
__device__ float  g_attn[MAXB * (size_t)N_DIM * N_DIM];  // S fp32 (268 MB)
__device__ __half g_ps[MAXB * (size_t)N_DIM * N_DIM];    // P single fp16 (134 MB)

// ============================================================================
// Helpers
// ============================================================================
__device__ __forceinline__ void split_store2(__half* Ch, __half* Cl,
                                             size_t o, float x, float y)
{
    __half hx = __float2half(x);
    __half hy = __float2half(y);
    __half lx = __float2half(x - __half2float(hx));
    __half ly = __float2half(y - __half2float(hy));
    __half2 th(hx, hy);
    __half2 tl(lx, ly);
    *(u32*)&Ch[o] = *(u32*)&th;
    *(u32*)&Cl[o] = *(u32*)&tl;
}

__device__ __forceinline__ void single_store2(__half* C, size_t o, float x, float y)
{
    __half2 t(__float2half(x), __float2half(y));
    *(u32*)&C[o] = *(u32*)&t;
}

__device__ __forceinline__ u32 saddr(const void* p)
{
    return (u32)__cvta_generic_to_shared(p);
}

__device__ __forceinline__ void cp16(u32 dst, const void* src)
{
    asm volatile("cp.async.cg.shared.global [%0], [%1], 16;\n" :: "r"(dst), "l"(src));
}
__device__ __forceinline__ void cp_commit()
{
    asm volatile("cp.async.commit_group;\n");
}
template <int NN_>
__device__ __forceinline__ void cp_wait()
{
    asm volatile("cp.async.wait_group %0;\n" :: "n"(NN_));
}

__device__ __forceinline__ void ldsm4(u32* r, u32 a)
{
    asm volatile("ldmatrix.sync.aligned.m8n8.x4.shared.b16 {%0,%1,%2,%3}, [%4];\n"
        : "=r"(r[0]), "=r"(r[1]), "=r"(r[2]), "=r"(r[3]) : "r"(a));
}
__device__ __forceinline__ void ldsm4t(u32* r, u32 a)
{
    asm volatile("ldmatrix.sync.aligned.m8n8.x4.trans.shared.b16 {%0,%1,%2,%3}, [%4];\n"
        : "=r"(r[0]), "=r"(r[1]), "=r"(r[2]), "=r"(r[3]) : "r"(a));
}
__device__ __forceinline__ void mma_f16(float* c, const u32* a, u32 b0, u32 b1)
{
    asm volatile(
        "mma.sync.aligned.m16n8k16.row.col.f32.f16.f16.f32 "
        "{%0,%1,%2,%3}, {%4,%5,%6,%7}, {%8,%9}, {%0,%1,%2,%3};\n"
        : "+f"(c[0]), "+f"(c[1]), "+f"(c[2]), "+f"(c[3])
        : "r"(a[0]), "r"(a[1]), "r"(a[2]), "r"(a[3]), "r"(b0), "r"(b1));
}

// ============================================================================
// fp32 -> split fp16 (weights)
// ============================================================================
__global__ void split_kernel(const float* __restrict__ in,
                             __half* __restrict__ h,
                             __half* __restrict__ l, int n4)
{
    int i = blockIdx.x * blockDim.x + threadIdx.x;
    if (i >= n4) return;
    float4 v = ((const float4*)in)[i];
    split_store2(h, l, (size_t)i * 4,     v.x, v.y);
    split_store2(h, l, (size_t)i * 4 + 2, v.z, v.w);
}

// ============================================================================
// GroupNorm: 32 groups, 16 ch/group, eps=1e-5; writes split fp16
// ============================================================================
__global__ void groupnorm_kernel(const float* __restrict__ x,
                                 const float* __restrict__ w,
                                 const float* __restrict__ b,
                                 __half* __restrict__ oh,
                                 __half* __restrict__ ol)
{
    const int CPG = 16;
    const int CNT = CPG * N_DIM;
    int bg = blockIdx.x;
    int g  = bg & 31;
    int bb = bg >> 5;
    size_t base = ((size_t)bb * C_DIM + (size_t)g * CPG) * N_DIM;
    const float4* x4 = (const float4*)(x + base);
    int tid = threadIdx.x;

    float s = 0.f, ss = 0.f;
    for (int i = tid; i < CNT / 4; i += blockDim.x) {
        float4 v = x4[i];
        s  += v.x + v.y + v.z + v.w;
        ss += v.x * v.x + v.y * v.y + v.z * v.z + v.w * v.w;
    }
    __shared__ float rs[8], rss[8];
    #pragma unroll
    for (int o = 16; o; o >>= 1) {
        s  += __shfl_xor_sync(0xffffffffu, s,  o);
        ss += __shfl_xor_sync(0xffffffffu, ss, o);
    }
    int wid = tid >> 5;
    int lid = tid & 31;
    if (lid == 0) { rs[wid] = s; rss[wid] = ss; }
    __syncthreads();
    if (tid == 0) {
        float ts = 0.f, tss = 0.f;
        int nw = blockDim.x >> 5;
        for (int i = 0; i < nw; i++) { ts += rs[i]; tss += rss[i]; }
        rs[0] = ts; rss[0] = tss;
    }
    __syncthreads();
    float mu   = rs[0] / (float)CNT;
    float var  = rss[0] / (float)CNT - mu * mu;
    float rsig = rsqrtf(var + 1e-5f);

    for (int i = tid; i < CNT / 4; i += blockDim.x) {
        int c = g * CPG + (i >> 10);
        float sc = w[c] * rsig;
        float sh = b[c] - mu * sc;
        float4 v = x4[i];
        size_t o = base + (size_t)i * 4;
        split_store2(oh, ol, o,     v.x * sc + sh, v.y * sc + sh);
        split_store2(oh, ol, o + 2, v.z * sc + sh, v.w * sc + sh);
    }
}

// ============================================================================
// Pipelined split-fp16 tensor-core GEMM (cp.async, 2 stages, 2 CTAs/SM).
//   C[m,n] = alpha * sum_k A(m,k)*B(k,n)
//   A is ALWAYS hi/lo split. B is split iff BSP.
//   MMA terms: ah*bh + (BSP? ah*bl) + al*bh  (3 or 2 MMAs)
//   TA/TB as before. OMODE: 0 = fp32 out (+bias,+res)
//                           1 = split fp16 out (Ch,Cl)
//                           2 = fused-QKV routing (blockIdx.y: 0-3=q,4-7=k,8-11=v)
// BM=BN=128, BK=32, 256 threads (8 warps 2x4), warp tile 64x32.
// ============================================================================
#define NSTAGE 2

template <bool TA, bool TB, int BSP, int OMODE>
__global__ __launch_bounds__(256, 2)
void pgemm_kernel(const __half* __restrict__ Agh,
                  const __half* __restrict__ Agl,
                  const __half* __restrict__ Bgh,
                  const __half* __restrict__ Bgl,
                  float* __restrict__ Cf,
                  __half* __restrict__ Ch,
                  __half* __restrict__ Cl,
                  __half* __restrict__ Ks,
                  __half* __restrict__ Vh,
                  __half* __restrict__ Vl,
                  int K, int lda, int ldb, int ldc,
                  long long sA, long long sB, long long sC,
                  const float* __restrict__ bias,
                  const float* __restrict__ bias2,
                  const float* __restrict__ bias3,
                  const float* __restrict__ res, long long sRes,
                  float alpha)
{
    const int BK = 32;
    const int AST = TA ? 136 : 40;
    const int BST = TB ? 40 : 136;
    const int ASZ = TA ? (BK * AST) : (128 * AST);
    const int BSZ = TB ? (128 * BST) : (BK * BST);
    const int STAGE = 2 * ASZ + (1 + BSP) * BSZ;

    extern __shared__ __align__(16) char smraw[];
    __half* sm = (__half*)smraw;

    int z = blockIdx.z;
    Agh += (long long)z * sA;
    Agl += (long long)z * sA;
    Bgh += (long long)z * sB;
    if (BSP) Bgl += (long long)z * sB;

    int sel = 0;
    int m0;
    if (OMODE == 2) {
        sel = blockIdx.y >> 2;
        m0  = (blockIdx.y & 3) * 128;
        long long wo = (long long)sel * C_DIM * C_DIM;
        Agh += wo;
        Agl += wo;
        Ch += (long long)z * sC;
        Cl += (long long)z * sC;
        Ks += (long long)z * sC;
        Vh += (long long)z * sC;
        Vl += (long long)z * sC;
    } else {
        m0 = blockIdx.y * 128;
        if (OMODE == 1) { Ch += (long long)z * sC; Cl += (long long)z * sC; }
        else            { Cf += (long long)z * sC; }
        if (OMODE == 0 && res) res += (long long)z * sRes;
    }

    int n0 = blockIdx.x * 128;
    int tid  = threadIdx.x;
    int lane = tid & 31;
    int wid  = tid >> 5;
    int m_w = (wid >> 2) * 64;
    int n_w = (wid & 3) * 32;

    int a_base, b_base;
    if (!TA) {
        a_base = (m_w + (lane & 15)) * AST + ((lane >> 4) * 8);
    } else {
        a_base = (((lane >> 4) & 1) * 8 + (lane & 7)) * AST
               + m_w + ((lane >> 3) & 1) * 8;
    }
    if (!TB) {
        b_base = (((lane >> 3) & 1) * 8 + (lane & 7)) * BST
               + n_w + ((lane >> 4) & 1) * 8;
    } else {
        b_base = (n_w + ((lane >> 4) & 1) * 8 + (lane & 7)) * BST
               + ((lane >> 3) & 1) * 8;
    }

    float c[4][4][4];
    #pragma unroll
    for (int i = 0; i < 4; i++) {
        #pragma unroll
        for (int j = 0; j < 4; j++) {
            #pragma unroll
            for (int t = 0; t < 4; t++) c[i][j][t] = 0.f;
        }
    }

    int KT = K / BK;

    auto load_stage = [&](int st, int k0) {
        __half* sAh = sm + st * STAGE;
        __half* sAl = sAh + ASZ;
        __half* sBh = sAl + ASZ;
        __half* sBl = sBh + BSZ;       // only valid if BSP
        #pragma unroll
        for (int r = 0; r < 2; r++) {
            int i = tid + r * 256;
            if (!TA) {
                int m  = i >> 2;
                int kq = (i & 3) * 8;
                size_t go = (size_t)(m0 + m) * lda + k0 + kq;
                int    so = m * AST + kq;
                cp16(saddr(sAh + so), Agh + go);
                cp16(saddr(sAl + so), Agl + go);
            } else {
                int k  = i >> 4;
                int mq = (i & 15) * 8;
                size_t go = (size_t)(k0 + k) * lda + m0 + mq;
                int    so = k * AST + mq;
                cp16(saddr(sAh + so), Agh + go);
                cp16(saddr(sAl + so), Agl + go);
            }
            if (!TB) {
                int k  = i >> 4;
                int nq = (i & 15) * 8;
                size_t go = (size_t)(k0 + k) * ldb + n0 + nq;
                int    so = k * BST + nq;
                cp16(saddr(sBh + so), Bgh + go);
                if (BSP) cp16(saddr(sBl + so), Bgl + go);
            } else {
                int n  = i >> 2;
                int kq = (i & 3) * 8;
                size_t go = (size_t)(n0 + n) * ldb + k0 + kq;
                int    so = n * BST + kq;
                cp16(saddr(sBh + so), Bgh + go);
                if (BSP) cp16(saddr(sBl + so), Bgl + go);
            }
        }
    };

    #pragma unroll
    for (int s = 0; s < NSTAGE - 1; s++) {
        if (s < KT) load_stage(s, s * BK);
        cp_commit();
    }

    for (int kt = 0; kt < KT; kt++) {
        cp_wait<NSTAGE - 2>();
        __syncthreads();

        int pf = kt + NSTAGE - 1;
        if (pf < KT) load_stage(pf % NSTAGE, pf * BK);
        cp_commit();

        int st = kt % NSTAGE;
        const __half* pAh = sm + st * STAGE;
        const __half* pAl = pAh + ASZ;
        const __half* pBh = pAl + ASZ;
        const __half* pBl = pBh + BSZ;

        #pragma unroll
        for (int ks = 0; ks < 2; ks++) {
            int aoff = a_base + (TA ? ks * 16 * AST : ks * 16);
            int boff = b_base + (TB ? ks * 16 : ks * 16 * BST);

            u32 ah[4][4], al[4][4], bh[2][4], bl[2][4];
            #pragma unroll
            for (int mt = 0; mt < 4; mt++) {
                int o = aoff + (TA ? mt * 16 : mt * 16 * AST);
                if (TA) {
                    ldsm4t(ah[mt], saddr(pAh + o));
                    ldsm4t(al[mt], saddr(pAl + o));
                } else {
                    ldsm4(ah[mt], saddr(pAh + o));
                    ldsm4(al[mt], saddr(pAl + o));
                }
            }
            #pragma unroll
            for (int p = 0; p < 2; p++) {
                int o = boff + (TB ? p * 16 * BST : p * 16);
                if (TB) {
                    ldsm4(bh[p], saddr(pBh + o));
                    if (BSP) ldsm4(bl[p], saddr(pBl + o));
                } else {
                    ldsm4t(bh[p], saddr(pBh + o));
                    if (BSP) ldsm4t(bl[p], saddr(pBl + o));
                }
            }
            #pragma unroll
            for (int mt = 0; mt < 4; mt++) {
                #pragma unroll
                for (int nt = 0; nt < 4; nt++) {
                    int p = nt >> 1;
                    int q = (nt & 1) * 2;
                    mma_f16(c[mt][nt], ah[mt], bh[p][q], bh[p][q + 1]);
                    if (BSP) mma_f16(c[mt][nt], ah[mt], bl[p][q], bl[p][q + 1]);
                    mma_f16(c[mt][nt], al[mt], bh[p][q], bh[p][q + 1]);
                }
            }
        }
        __syncthreads();
    }

    // ---- epilogue ----
    const float* bp_ = bias;
    __half* Ho = Ch;
    __half* Lo = Cl;
    if (OMODE == 2) {
        if (sel == 1)      { bp_ = bias2; Ho = Ks;  Lo = 0;  }
        else if (sel == 2) { bp_ = bias3; Ho = Vh;  Lo = Vl; }
    }

    int g  = lane >> 2;
    int tq = lane & 3;
    #pragma unroll
    for (int mt = 0; mt < 4; mt++) {
        int mr0 = m0 + m_w + mt * 16 + g;
        int mr1 = mr0 + 8;
        float b0v = bp_ ? bp_[mr0] : 0.f;
        float b1v = bp_ ? bp_[mr1] : 0.f;
        #pragma unroll
        for (int nt = 0; nt < 4; nt++) {
            int nc = n0 + n_w + nt * 8 + tq * 2;
            size_t o0 = (size_t)mr0 * ldc + nc;
            size_t o1 = (size_t)mr1 * ldc + nc;
            float v00 = c[mt][nt][0] * alpha + b0v;
            float v01 = c[mt][nt][1] * alpha + b0v;
            float v10 = c[mt][nt][2] * alpha + b1v;
            float v11 = c[mt][nt][3] * alpha + b1v;
            if (OMODE == 0) {
                if (res) {
                    float2 r0 = *(const float2*)&res[o0];
                    float2 r1 = *(const float2*)&res[o1];
                    v00 += r0.x; v01 += r0.y;
                    v10 += r1.x; v11 += r1.y;
                }
                float2 w0; w0.x = v00; w0.y = v01;
                float2 w1; w1.x = v10; w1.y = v11;
                *(float2*)&Cf[o0] = w0;
                *(float2*)&Cf[o1] = w1;
            } else if (OMODE == 1) {
                split_store2(Ch, Cl, o0, v00, v01);
                split_store2(Ch, Cl, o1, v10, v11);
            } else {
                if (sel == 1) {
                    single_store2(Ho, o0, v00, v01);
                    single_store2(Ho, o1, v10, v11);
                } else {
                    split_store2(Ho, Lo, o0, v00, v01);
                    split_store2(Ho, Lo, o1, v10, v11);
                }
            }
        }
    }
}

// ============================================================================
// Row softmax over attn[b,i,:] (4096), writes single fp16 P.
// ============================================================================
__global__ void softmax_kernel(const float* __restrict__ attn,
                               __half* __restrict__ ps)
{
    size_t row = blockIdx.x;
    const float4* p = (const float4*)(attn + row * N_DIM);
    int tid = threadIdx.x;
    __shared__ float sh[8];

    float4 r[4];
    float mx = -1e30f;
    #pragma unroll
    for (int i = 0; i < 4; i++) {
        r[i] = p[tid + i * 256];
        mx = fmaxf(mx, fmaxf(fmaxf(r[i].x, r[i].y), fmaxf(r[i].z, r[i].w)));
    }
    #pragma unroll
    for (int o = 16; o; o >>= 1) mx = fmaxf(mx, __shfl_xor_sync(0xffffffffu, mx, o));
    if ((tid & 31) == 0) sh[tid >> 5] = mx;
    __syncthreads();
    if (tid == 0) {
        float t = sh[0];
        for (int i = 1; i < 8; i++) t = fmaxf(t, sh[i]);
        sh[0] = t;
    }
    __syncthreads();
    mx = sh[0];
    __syncthreads();

    float sum = 0.f;
    #pragma unroll
    for (int i = 0; i < 4; i++) {
        r[i].x = __expf(r[i].x - mx);
        r[i].y = __expf(r[i].y - mx);
        r[i].z = __expf(r[i].z - mx);
        r[i].w = __expf(r[i].w - mx);
        sum += r[i].x + r[i].y + r[i].z + r[i].w;
    }
    #pragma unroll
    for (int o = 16; o; o >>= 1) sum += __shfl_xor_sync(0xffffffffu, sum, o);
    if ((tid & 31) == 0) sh[tid >> 5] = sum;
    __syncthreads();
    if (tid == 0) {
        float t = 0.f;
        for (int i = 0; i < 8; i++) t += sh[i];
        sh[0] = t;
    }
    __syncthreads();
    float inv = 1.f / sh[0];

    #pragma unroll
    for (int i = 0; i < 4; i++) {
        size_t o = row * N_DIM + (size_t)(tid + i * 256) * 4;
        single_store2(ps, o,     r[i].x * inv, r[i].y * inv);
        single_store2(ps, o + 2, r[i].z * inv, r[i].w * inv);
    }
}

// ============================================================================
// Host launcher
// ============================================================================
static int stage_elems(bool ta, bool tb, int bsp)
{
    int AST = ta ? 136 : 40;
    int BST = tb ? 40 : 136;
    int ASZ = ta ? (32 * AST) : (128 * AST);
    int BSZ = tb ? (128 * BST) : (32 * BST);
    return 2 * ASZ + (1 + bsp) * BSZ;
}

extern "C" void kernel_launch(void* const* d_in, const int* in_sizes, int n_in,
                              void* d_out, int out_size)
{
    const float* x   = (const float*)d_in[0];
    const float* gnw = (const float*)d_in[1];
    const float* gnb = (const float*)d_in[2];
    const float* wq  = (const float*)d_in[3];
    const float* bq  = (const float*)d_in[4];
    const float* wk  = (const float*)d_in[5];
    const float* bk  = (const float*)d_in[6];
    const float* wv  = (const float*)d_in[7];
    const float* bv  = (const float*)d_in[8];
    const float* wp  = (const float*)d_in[9];
    const float* bp  = (const float*)d_in[10];
    float* out = (float*)d_out;

    int B = in_sizes[0] / (C_DIM * N_DIM);
    if (B < 1) B = 1;
    if (B > MAXB) B = MAXB;

    __half *xh, *xl, *qh, *ql, *ks, *vh, *vl, *oh, *ol, *wh, *wl, *ps;
    float* attn;
    cudaGetSymbolAddress((void**)&xh, g_xh);
    cudaGetSymbolAddress((void**)&xl, g_xl);
    cudaGetSymbolAddress((void**)&qh, g_qh);
    cudaGetSymbolAddress((void**)&ql, g_ql);
    cudaGetSymbolAddress((void**)&ks, g_ks);
    cudaGetSymbolAddress((void**)&vh, g_vh);
    cudaGetSymbolAddress((void**)&vl, g_vl);
    cudaGetSymbolAddress((void**)&oh, g_oh);
    cudaGetSymbolAddress((void**)&ol, g_ol);
    cudaGetSymbolAddress((void**)&wh, g_wh);
    cudaGetSymbolAddress((void**)&wl, g_wl);
    cudaGetSymbolAddress((void**)&ps, g_ps);
    cudaGetSymbolAddress((void**)&attn, g_attn);

    const long long CN = (long long)C_DIM * N_DIM;
    const long long NN = (long long)N_DIM * N_DIM;
    const long long CC = (long long)C_DIM * C_DIM;
    const float scale = 1.0f / sqrtf((float)C_DIM);

    int smQKV  = NSTAGE * stage_elems(false, false, 1) * 2;
    int smS    = NSTAGE * stage_elems(true,  false, 0) * 2;
    int smPV   = NSTAGE * stage_elems(false, true,  0) * 2;
    int smPROJ = smQKV;
    cudaFuncSetAttribute(pgemm_kernel<false, false, 1, 2>,
                         cudaFuncAttributeMaxDynamicSharedMemorySize, smQKV);
    cudaFuncSetAttribute(pgemm_kernel<true, false, 0, 0>,
                         cudaFuncAttributeMaxDynamicSharedMemorySize, smS);
    cudaFuncSetAttribute(pgemm_kernel<false, true, 0, 1>,
                         cudaFuncAttributeMaxDynamicSharedMemorySize, smPV);
    cudaFuncSetAttribute(pgemm_kernel<false, false, 1, 0>,
                         cudaFuncAttributeMaxDynamicSharedMemorySize, smPROJ);

    // 1) GroupNorm -> split xn
    groupnorm_kernel<<<B * 32, 256>>>(x, gnw, gnb, xh, xl);

    // 2) Split the 4 weight matrices (q,k,v,p stacked)
    {
        int n4 = C_DIM * C_DIM / 4;
        int tb = 256, gb = (n4 + tb - 1) / tb;
        split_kernel<<<gb, tb>>>(wq, wh + 0 * CC, wl + 0 * CC, n4);
        split_kernel<<<gb, tb>>>(wk, wh + 1 * CC, wl + 1 * CC, n4);
        split_kernel<<<gb, tb>>>(wv, wh + 2 * CC, wl + 2 * CC, n4);
        split_kernel<<<gb, tb>>>(wp, wh + 3 * CC, wl + 3 * CC, n4);
    }

    // 3) Fused QKV projection: one launch, grid.y routes q/k/v
    {
        dim3 grid(N_DIM / 128, 12, B);
        pgemm_kernel<false, false, 1, 2><<<grid, 256, smQKV>>>(
            wh, wl, xh, xl,
            (float*)0, qh, ql, ks, vh, vl,
            C_DIM, C_DIM, N_DIM, N_DIM, 0, CN, CN,
            bq, bk, bv, (const float*)0, 0, 1.0f);
    }

    // 4) Scores: S[i,j] = scale * sum_c q[c,i] k[c,j]  (A=q split, B=k single)
    {
        dim3 grid(N_DIM / 128, N_DIM / 128, B);
        pgemm_kernel<true, false, 0, 0><<<grid, 256, smS>>>(
            qh, ql, ks, (const __half*)0,
            attn, (__half*)0, (__half*)0, (__half*)0, (__half*)0, (__half*)0,
            C_DIM, N_DIM, N_DIM, N_DIM, CN, CN, NN,
            (const float*)0, (const float*)0, (const float*)0,
            (const float*)0, 0, scale);
    }

    // 5) Softmax -> single fp16 P
    softmax_kernel<<<B * N_DIM, 256>>>(attn, ps);

    // 6) out[c,i] = sum_j v[c,j] * P[i,j]  (A=v split, B=P single, split out)
    {
        dim3 grid(N_DIM / 128, C_DIM / 128, B);
        pgemm_kernel<false, true, 0, 1><<<grid, 256, smPV>>>(
            vh, vl, ps, (const __half*)0,
            (float*)0, oh, ol, (__half*)0, (__half*)0, (__half*)0,
            N_DIM, N_DIM, N_DIM, N_DIM, CN, NN, CN,
            (const float*)0, (const float*)0, (const float*)0,
            (const float*)0, 0, 1.0f);
    }

    // 7) Projection + bias + residual -> d_out (fp32)
    {
        dim3 grid(N_DIM / 128, C_DIM / 128, B);
        pgemm_kernel<false, false, 1, 0><<<grid, 256, smPROJ>>>(
            wh + 3 * CC, wl + 3 * CC, oh, ol,
            out, (__half*)0, (__half*)0, (__half*)0, (__half*)0, (__half*)0,
            C_DIM, C_DIM, N_DIM, N_DIM, 0, CN, CN,
            bp, (const float*)0, (const float*)0, x, CN, 1.0f);
    }
}

// round 9
// speedup vs baseline: 4.5406x; 1.3575x over previous
#include <cuda_runtime.h>
#include <cuda_fp16.h>
#include <stdint.h>
#include <math.h>

typedef unsigned int u32;

#define C_DIM 512
#define N_DIM 4096
#define MAXB  4

// -------- scratch (__device__ globals) --------------------------------------
__device__ __half g_xh[MAXB * C_DIM * N_DIM];   // xn hi
__device__ __half g_xl[MAXB * C_DIM * N_DIM];   // xn lo
__device__ __half g_qs[MAXB * C_DIM * N_DIM];   // q single fp16
__device__ __half g_ks[MAXB * C_DIM * N_DIM];   // k single fp16
__device__ __half g_vs[MAXB * C_DIM * N_DIM];   // v single fp16
__device__ __half g_oh[MAXB * C_DIM * N_DIM];   // attn-out hi
__device__ __half g_ol[MAXB * C_DIM * N_DIM];   // attn-out lo
__device__ __half g_wh[4 * C_DIM * C_DIM];      // weights hi (q,k,v,p stacked)
__device__ __half g_wl[4 * C_DIM * C_DIM];      // weights lo
__device__ float  g_attn[MAXB * (size_t)N_DIM * N_DIM];  // S fp32 (268 MB)
__device__ __half g_ps[MAXB * (size_t)N_DIM * N_DIM];    // P single fp16 (134 MB)

// ============================================================================
// Helpers
// ============================================================================
__device__ __forceinline__ void split_store2(__half* Ch, __half* Cl,
                                             size_t o, float x, float y)
{
    __half hx = __float2half(x);
    __half hy = __float2half(y);
    __half lx = __float2half(x - __half2float(hx));
    __half ly = __float2half(y - __half2float(hy));
    __half2 th(hx, hy);
    __half2 tl(lx, ly);
    *(u32*)&Ch[o] = *(u32*)&th;
    *(u32*)&Cl[o] = *(u32*)&tl;
}

__device__ __forceinline__ void single_store2(__half* C, size_t o, float x, float y)
{
    __half2 t(__float2half(x), __float2half(y));
    *(u32*)&C[o] = *(u32*)&t;
}

__device__ __forceinline__ u32 saddr(const void* p)
{
    return (u32)__cvta_generic_to_shared(p);
}

__device__ __forceinline__ void cp16(u32 dst, const void* src)
{
    asm volatile("cp.async.cg.shared.global [%0], [%1], 16;\n" :: "r"(dst), "l"(src));
}
__device__ __forceinline__ void cp_commit()
{
    asm volatile("cp.async.commit_group;\n");
}
template <int NN_>
__device__ __forceinline__ void cp_wait()
{
    asm volatile("cp.async.wait_group %0;\n" :: "n"(NN_));
}

__device__ __forceinline__ void ldsm4(u32* r, u32 a)
{
    asm volatile("ldmatrix.sync.aligned.m8n8.x4.shared.b16 {%0,%1,%2,%3}, [%4];\n"
        : "=r"(r[0]), "=r"(r[1]), "=r"(r[2]), "=r"(r[3]) : "r"(a));
}
__device__ __forceinline__ void ldsm4t(u32* r, u32 a)
{
    asm volatile("ldmatrix.sync.aligned.m8n8.x4.trans.shared.b16 {%0,%1,%2,%3}, [%4];\n"
        : "=r"(r[0]), "=r"(r[1]), "=r"(r[2]), "=r"(r[3]) : "r"(a));
}
__device__ __forceinline__ void mma_f16(float* c, const u32* a, u32 b0, u32 b1)
{
    asm volatile(
        "mma.sync.aligned.m16n8k16.row.col.f32.f16.f16.f32 "
        "{%0,%1,%2,%3}, {%4,%5,%6,%7}, {%8,%9}, {%0,%1,%2,%3};\n"
        : "+f"(c[0]), "+f"(c[1]), "+f"(c[2]), "+f"(c[3])
        : "r"(a[0]), "r"(a[1]), "r"(a[2]), "r"(a[3]), "r"(b0), "r"(b1));
}

// ============================================================================
// fp32 -> split fp16 (weights)
// ============================================================================
__global__ void split_kernel(const float* __restrict__ in,
                             __half* __restrict__ h,
                             __half* __restrict__ l, int n4)
{
    int i = blockIdx.x * blockDim.x + threadIdx.x;
    if (i >= n4) return;
    float4 v = ((const float4*)in)[i];
    split_store2(h, l, (size_t)i * 4,     v.x, v.y);
    split_store2(h, l, (size_t)i * 4 + 2, v.z, v.w);
}

// ============================================================================
// GroupNorm: 32 groups, 16 ch/group, eps=1e-5; writes split fp16
// ============================================================================
__global__ void groupnorm_kernel(const float* __restrict__ x,
                                 const float* __restrict__ w,
                                 const float* __restrict__ b,
                                 __half* __restrict__ oh,
                                 __half* __restrict__ ol)
{
    const int CPG = 16;
    const int CNT = CPG * N_DIM;
    int bg = blockIdx.x;
    int g  = bg & 31;
    int bb = bg >> 5;
    size_t base = ((size_t)bb * C_DIM + (size_t)g * CPG) * N_DIM;
    const float4* x4 = (const float4*)(x + base);
    int tid = threadIdx.x;

    float s = 0.f, ss = 0.f;
    for (int i = tid; i < CNT / 4; i += blockDim.x) {
        float4 v = x4[i];
        s  += v.x + v.y + v.z + v.w;
        ss += v.x * v.x + v.y * v.y + v.z * v.z + v.w * v.w;
    }
    __shared__ float rs[8], rss[8];
    #pragma unroll
    for (int o = 16; o; o >>= 1) {
        s  += __shfl_xor_sync(0xffffffffu, s,  o);
        ss += __shfl_xor_sync(0xffffffffu, ss, o);
    }
    int wid = tid >> 5;
    int lid = tid & 31;
    if (lid == 0) { rs[wid] = s; rss[wid] = ss; }
    __syncthreads();
    if (tid == 0) {
        float ts = 0.f, tss = 0.f;
        int nw = blockDim.x >> 5;
        for (int i = 0; i < nw; i++) { ts += rs[i]; tss += rss[i]; }
        rs[0] = ts; rss[0] = tss;
    }
    __syncthreads();
    float mu   = rs[0] / (float)CNT;
    float var  = rss[0] / (float)CNT - mu * mu;
    float rsig = rsqrtf(var + 1e-5f);

    for (int i = tid; i < CNT / 4; i += blockDim.x) {
        int c = g * CPG + (i >> 10);
        float sc = w[c] * rsig;
        float sh = b[c] - mu * sc;
        float4 v = x4[i];
        size_t o = base + (size_t)i * 4;
        split_store2(oh, ol, o,     v.x * sc + sh, v.y * sc + sh);
        split_store2(oh, ol, o + 2, v.z * sc + sh, v.w * sc + sh);
    }
}

// ============================================================================
// Pipelined fp16 tensor-core GEMM (cp.async, 2 stages, 2 CTAs/SM).
//   C[m,n] = alpha * sum_k A(m,k)*B(k,n)
//   ASP: A has lo compensation term. BSP: B has lo term.
//   MMA terms: ah*bh + (BSP? ah*bl) + (ASP? al*bh)   (1..3 MMAs)
//   TA/TB: operand storage orientation (as before).
//   OMODE: 0 = fp32 out (+bias,+res)
//          1 = split fp16 out (Ch,Cl)
//          2 = fused-QKV routing (blockIdx.y: 0-3=q,4-7=k,8-11=v; all single)
// BM=BN=128, BK=32, 256 threads (8 warps 2x4), warp tile 64x32.
// ============================================================================
#define NSTAGE 2

template <bool TA, bool TB, int ASP, int BSP, int OMODE>
__global__ __launch_bounds__(256, 2)
void pgemm_kernel(const __half* __restrict__ Agh,
                  const __half* __restrict__ Agl,
                  const __half* __restrict__ Bgh,
                  const __half* __restrict__ Bgl,
                  float* __restrict__ Cf,
                  __half* __restrict__ Ch,
                  __half* __restrict__ Cl,
                  __half* __restrict__ Qs,
                  __half* __restrict__ Ks,
                  __half* __restrict__ Vs,
                  int K, int lda, int ldb, int ldc,
                  long long sA, long long sB, long long sC,
                  const float* __restrict__ bias,
                  const float* __restrict__ bias2,
                  const float* __restrict__ bias3,
                  const float* __restrict__ res, long long sRes,
                  float alpha)
{
    const int BK = 32;
    const int AST = TA ? 136 : 40;
    const int BST = TB ? 40 : 136;
    const int ASZ = TA ? (BK * AST) : (128 * AST);
    const int BSZ = TB ? (128 * BST) : (BK * BST);
    const int STAGE = (1 + ASP) * ASZ + (1 + BSP) * BSZ;

    extern __shared__ __align__(16) char smraw[];
    __half* sm = (__half*)smraw;

    int z = blockIdx.z;
    Agh += (long long)z * sA;
    if (ASP) Agl += (long long)z * sA;
    Bgh += (long long)z * sB;
    if (BSP) Bgl += (long long)z * sB;

    int sel = 0;
    int m0;
    if (OMODE == 2) {
        sel = blockIdx.y >> 2;
        m0  = (blockIdx.y & 3) * 128;
        long long wo = (long long)sel * C_DIM * C_DIM;
        Agh += wo;
        if (ASP) Agl += wo;
        Qs += (long long)z * sC;
        Ks += (long long)z * sC;
        Vs += (long long)z * sC;
    } else {
        m0 = blockIdx.y * 128;
        if (OMODE == 1) { Ch += (long long)z * sC; Cl += (long long)z * sC; }
        else            { Cf += (long long)z * sC; }
        if (OMODE == 0 && res) res += (long long)z * sRes;
    }

    int n0 = blockIdx.x * 128;
    int tid  = threadIdx.x;
    int lane = tid & 31;
    int wid  = tid >> 5;
    int m_w = (wid >> 2) * 64;
    int n_w = (wid & 3) * 32;

    int a_base, b_base;
    if (!TA) {
        a_base = (m_w + (lane & 15)) * AST + ((lane >> 4) * 8);
    } else {
        a_base = (((lane >> 4) & 1) * 8 + (lane & 7)) * AST
               + m_w + ((lane >> 3) & 1) * 8;
    }
    if (!TB) {
        b_base = (((lane >> 3) & 1) * 8 + (lane & 7)) * BST
               + n_w + ((lane >> 4) & 1) * 8;
    } else {
        b_base = (n_w + ((lane >> 4) & 1) * 8 + (lane & 7)) * BST
               + ((lane >> 3) & 1) * 8;
    }

    float c[4][4][4];
    #pragma unroll
    for (int i = 0; i < 4; i++) {
        #pragma unroll
        for (int j = 0; j < 4; j++) {
            #pragma unroll
            for (int t = 0; t < 4; t++) c[i][j][t] = 0.f;
        }
    }

    int KT = K / BK;

    auto load_stage = [&](int st, int k0) {
        __half* sAh = sm + st * STAGE;
        __half* sAl = sAh + ASZ;                      // valid iff ASP
        __half* sBh = sAh + (1 + ASP) * ASZ;
        __half* sBl = sBh + BSZ;                      // valid iff BSP
        #pragma unroll
        for (int r = 0; r < 2; r++) {
            int i = tid + r * 256;
            if (!TA) {
                int m  = i >> 2;
                int kq = (i & 3) * 8;
                size_t go = (size_t)(m0 + m) * lda + k0 + kq;
                int    so = m * AST + kq;
                cp16(saddr(sAh + so), Agh + go);
                if (ASP) cp16(saddr(sAl + so), Agl + go);
            } else {
                int k  = i >> 4;
                int mq = (i & 15) * 8;
                size_t go = (size_t)(k0 + k) * lda + m0 + mq;
                int    so = k * AST + mq;
                cp16(saddr(sAh + so), Agh + go);
                if (ASP) cp16(saddr(sAl + so), Agl + go);
            }
            if (!TB) {
                int k  = i >> 4;
                int nq = (i & 15) * 8;
                size_t go = (size_t)(k0 + k) * ldb + n0 + nq;
                int    so = k * BST + nq;
                cp16(saddr(sBh + so), Bgh + go);
                if (BSP) cp16(saddr(sBl + so), Bgl + go);
            } else {
                int n  = i >> 2;
                int kq = (i & 3) * 8;
                size_t go = (size_t)(n0 + n) * ldb + k0 + kq;
                int    so = n * BST + kq;
                cp16(saddr(sBh + so), Bgh + go);
                if (BSP) cp16(saddr(sBl + so), Bgl + go);
            }
        }
    };

    #pragma unroll
    for (int s = 0; s < NSTAGE - 1; s++) {
        if (s < KT) load_stage(s, s * BK);
        cp_commit();
    }

    for (int kt = 0; kt < KT; kt++) {
        cp_wait<NSTAGE - 2>();
        __syncthreads();

        int pf = kt + NSTAGE - 1;
        if (pf < KT) load_stage(pf % NSTAGE, pf * BK);
        cp_commit();

        int st = kt % NSTAGE;
        const __half* pAh = sm + st * STAGE;
        const __half* pAl = pAh + ASZ;
        const __half* pBh = pAh + (1 + ASP) * ASZ;
        const __half* pBl = pBh + BSZ;

        #pragma unroll
        for (int ks = 0; ks < 2; ks++) {
            int aoff = a_base + (TA ? ks * 16 * AST : ks * 16);
            int boff = b_base + (TB ? ks * 16 : ks * 16 * BST);

            u32 ah[4][4], al[4][4], bh[2][4], bl[2][4];
            #pragma unroll
            for (int mt = 0; mt < 4; mt++) {
                int o = aoff + (TA ? mt * 16 : mt * 16 * AST);
                if (TA) {
                    ldsm4t(ah[mt], saddr(pAh + o));
                    if (ASP) ldsm4t(al[mt], saddr(pAl + o));
                } else {
                    ldsm4(ah[mt], saddr(pAh + o));
                    if (ASP) ldsm4(al[mt], saddr(pAl + o));
                }
            }
            #pragma unroll
            for (int p = 0; p < 2; p++) {
                int o = boff + (TB ? p * 16 * BST : p * 16);
                if (TB) {
                    ldsm4(bh[p], saddr(pBh + o));
                    if (BSP) ldsm4(bl[p], saddr(pBl + o));
                } else {
                    ldsm4t(bh[p], saddr(pBh + o));
                    if (BSP) ldsm4t(bl[p], saddr(pBl + o));
                }
            }
            #pragma unroll
            for (int mt = 0; mt < 4; mt++) {
                #pragma unroll
                for (int nt = 0; nt < 4; nt++) {
                    int p = nt >> 1;
                    int q = (nt & 1) * 2;
                    mma_f16(c[mt][nt], ah[mt], bh[p][q], bh[p][q + 1]);
                    if (BSP) mma_f16(c[mt][nt], ah[mt], bl[p][q], bl[p][q + 1]);
                    if (ASP) mma_f16(c[mt][nt], al[mt], bh[p][q], bh[p][q + 1]);
                }
            }
        }
        __syncthreads();
    }

    // ---- epilogue ----
    const float* bp_ = bias;
    __half* So = Qs;
    if (OMODE == 2) {
        if (sel == 1)      { bp_ = bias2; So = Ks; }
        else if (sel == 2) { bp_ = bias3; So = Vs; }
    }

    int g  = lane >> 2;
    int tq = lane & 3;
    #pragma unroll
    for (int mt = 0; mt < 4; mt++) {
        int mr0 = m0 + m_w + mt * 16 + g;
        int mr1 = mr0 + 8;
        float b0v = bp_ ? bp_[mr0] : 0.f;
        float b1v = bp_ ? bp_[mr1] : 0.f;
        #pragma unroll
        for (int nt = 0; nt < 4; nt++) {
            int nc = n0 + n_w + nt * 8 + tq * 2;
            size_t o0 = (size_t)mr0 * ldc + nc;
            size_t o1 = (size_t)mr1 * ldc + nc;
            float v00 = c[mt][nt][0] * alpha + b0v;
            float v01 = c[mt][nt][1] * alpha + b0v;
            float v10 = c[mt][nt][2] * alpha + b1v;
            float v11 = c[mt][nt][3] * alpha + b1v;
            if (OMODE == 0) {
                if (res) {
                    float2 r0 = *(const float2*)&res[o0];
                    float2 r1 = *(const float2*)&res[o1];
                    v00 += r0.x; v01 += r0.y;
                    v10 += r1.x; v11 += r1.y;
                }
                float2 w0; w0.x = v00; w0.y = v01;
                float2 w1; w1.x = v10; w1.y = v11;
                *(float2*)&Cf[o0] = w0;
                *(float2*)&Cf[o1] = w1;
            } else if (OMODE == 1) {
                split_store2(Ch, Cl, o0, v00, v01);
                split_store2(Ch, Cl, o1, v10, v11);
            } else {
                single_store2(So, o0, v00, v01);
                single_store2(So, o1, v10, v11);
            }
        }
    }
}

// ============================================================================
// Row softmax over attn[b,i,:] (4096), writes single fp16 P.
// ============================================================================
__global__ void softmax_kernel(const float* __restrict__ attn,
                               __half* __restrict__ ps)
{
    size_t row = blockIdx.x;
    const float4* p = (const float4*)(attn + row * N_DIM);
    int tid = threadIdx.x;
    __shared__ float sh[8];

    float4 r[4];
    float mx = -1e30f;
    #pragma unroll
    for (int i = 0; i < 4; i++) {
        r[i] = p[tid + i * 256];
        mx = fmaxf(mx, fmaxf(fmaxf(r[i].x, r[i].y), fmaxf(r[i].z, r[i].w)));
    }
    #pragma unroll
    for (int o = 16; o; o >>= 1) mx = fmaxf(mx, __shfl_xor_sync(0xffffffffu, mx, o));
    if ((tid & 31) == 0) sh[tid >> 5] = mx;
    __syncthreads();
    if (tid == 0) {
        float t = sh[0];
        for (int i = 1; i < 8; i++) t = fmaxf(t, sh[i]);
        sh[0] = t;
    }
    __syncthreads();
    mx = sh[0];
    __syncthreads();

    float sum = 0.f;
    #pragma unroll
    for (int i = 0; i < 4; i++) {
        r[i].x = __expf(r[i].x - mx);
        r[i].y = __expf(r[i].y - mx);
        r[i].z = __expf(r[i].z - mx);
        r[i].w = __expf(r[i].w - mx);
        sum += r[i].x + r[i].y + r[i].z + r[i].w;
    }
    #pragma unroll
    for (int o = 16; o; o >>= 1) sum += __shfl_xor_sync(0xffffffffu, sum, o);
    if ((tid & 31) == 0) sh[tid >> 5] = sum;
    __syncthreads();
    if (tid == 0) {
        float t = 0.f;
        for (int i = 0; i < 8; i++) t += sh[i];
        sh[0] = t;
    }
    __syncthreads();
    float inv = 1.f / sh[0];

    #pragma unroll
    for (int i = 0; i < 4; i++) {
        size_t o = row * N_DIM + (size_t)(tid + i * 256) * 4;
        single_store2(ps, o,     r[i].x * inv, r[i].y * inv);
        single_store2(ps, o + 2, r[i].z * inv, r[i].w * inv);
    }
}

// ============================================================================
// Host launcher
// ============================================================================
static int stage_elems(bool ta, bool tb, int asp, int bsp)
{
    int AST = ta ? 136 : 40;
    int BST = tb ? 40 : 136;
    int ASZ = ta ? (32 * AST) : (128 * AST);
    int BSZ = tb ? (128 * BST) : (32 * BST);
    return (1 + asp) * ASZ + (1 + bsp) * BSZ;
}

extern "C" void kernel_launch(void* const* d_in, const int* in_sizes, int n_in,
                              void* d_out, int out_size)
{
    const float* x   = (const float*)d_in[0];
    const float* gnw = (const float*)d_in[1];
    const float* gnb = (const float*)d_in[2];
    const float* wq  = (const float*)d_in[3];
    const float* bq  = (const float*)d_in[4];
    const float* wk  = (const float*)d_in[5];
    const float* bk  = (const float*)d_in[6];
    const float* wv  = (const float*)d_in[7];
    const float* bv  = (const float*)d_in[8];
    const float* wp  = (const float*)d_in[9];
    const float* bp  = (const float*)d_in[10];
    float* out = (float*)d_out;

    int B = in_sizes[0] / (C_DIM * N_DIM);
    if (B < 1) B = 1;
    if (B > MAXB) B = MAXB;

    __half *xh, *xl, *qs, *ks, *vs, *oh, *ol, *wh, *wl, *ps;
    float* attn;
    cudaGetSymbolAddress((void**)&xh, g_xh);
    cudaGetSymbolAddress((void**)&xl, g_xl);
    cudaGetSymbolAddress((void**)&qs, g_qs);
    cudaGetSymbolAddress((void**)&ks, g_ks);
    cudaGetSymbolAddress((void**)&vs, g_vs);
    cudaGetSymbolAddress((void**)&oh, g_oh);
    cudaGetSymbolAddress((void**)&ol, g_ol);
    cudaGetSymbolAddress((void**)&wh, g_wh);
    cudaGetSymbolAddress((void**)&wl, g_wl);
    cudaGetSymbolAddress((void**)&ps, g_ps);
    cudaGetSymbolAddress((void**)&attn, g_attn);

    const long long CN = (long long)C_DIM * N_DIM;
    const long long NN = (long long)N_DIM * N_DIM;
    const long long CC = (long long)C_DIM * C_DIM;
    const float scale = 1.0f / sqrtf((float)C_DIM);

    int smQKV = NSTAGE * stage_elems(false, false, 1, 1) * 2;
    int smS   = NSTAGE * stage_elems(true,  false, 0, 0) * 2;
    int smPV  = NSTAGE * stage_elems(false, true,  0, 0) * 2;
    cudaFuncSetAttribute(pgemm_kernel<false, false, 1, 1, 2>,
                         cudaFuncAttributeMaxDynamicSharedMemorySize, smQKV);
    cudaFuncSetAttribute(pgemm_kernel<true, false, 0, 0, 0>,
                         cudaFuncAttributeMaxDynamicSharedMemorySize, smS);
    cudaFuncSetAttribute(pgemm_kernel<false, true, 0, 0, 1>,
                         cudaFuncAttributeMaxDynamicSharedMemorySize, smPV);
    cudaFuncSetAttribute(pgemm_kernel<false, false, 1, 1, 0>,
                         cudaFuncAttributeMaxDynamicSharedMemorySize, smQKV);

    // 1) GroupNorm -> split xn
    groupnorm_kernel<<<B * 32, 256>>>(x, gnw, gnb, xh, xl);

    // 2) Split the 4 weight matrices (q,k,v,p stacked)
    {
        int n4 = C_DIM * C_DIM / 4;
        int tb = 256, gb = (n4 + tb - 1) / tb;
        split_kernel<<<gb, tb>>>(wq, wh + 0 * CC, wl + 0 * CC, n4);
        split_kernel<<<gb, tb>>>(wk, wh + 1 * CC, wl + 1 * CC, n4);
        split_kernel<<<gb, tb>>>(wv, wh + 2 * CC, wl + 2 * CC, n4);
        split_kernel<<<gb, tb>>>(wp, wh + 3 * CC, wl + 3 * CC, n4);
    }

    // 3) Fused QKV projection (3-term): one launch, outputs single fp16 q/k/v
    {
        dim3 grid(N_DIM / 128, 12, B);
        pgemm_kernel<false, false, 1, 1, 2><<<grid, 256, smQKV>>>(
            wh, wl, xh, xl,
            (float*)0, (__half*)0, (__half*)0, qs, ks, vs,
            C_DIM, C_DIM, N_DIM, N_DIM, 0, CN, CN,
            bq, bk, bv, (const float*)0, 0, 1.0f);
    }

    // 4) Scores (1-term): S[i,j] = scale * sum_c q[c,i] k[c,j]
    {
        dim3 grid(N_DIM / 128, N_DIM / 128, B);
        pgemm_kernel<true, false, 0, 0, 0><<<grid, 256, smS>>>(
            qs, (const __half*)0, ks, (const __half*)0,
            attn, (__half*)0, (__half*)0, (__half*)0, (__half*)0, (__half*)0,
            C_DIM, N_DIM, N_DIM, N_DIM, CN, CN, NN,
            (const float*)0, (const float*)0, (const float*)0,
            (const float*)0, 0, scale);
    }

    // 5) Softmax -> single fp16 P
    softmax_kernel<<<B * N_DIM, 256>>>(attn, ps);

    // 6) PV (1-term): out[c,i] = sum_j v[c,j] * P[i,j]  (split out for proj)
    {
        dim3 grid(N_DIM / 128, C_DIM / 128, B);
        pgemm_kernel<false, true, 0, 0, 1><<<grid, 256, smPV>>>(
            vs, (const __half*)0, ps, (const __half*)0,
            (float*)0, oh, ol, (__half*)0, (__half*)0, (__half*)0,
            N_DIM, N_DIM, N_DIM, N_DIM, CN, NN, CN,
            (const float*)0, (const float*)0, (const float*)0,
            (const float*)0, 0, 1.0f);
    }

    // 7) Projection (3-term) + bias + residual -> d_out (fp32)
    {
        dim3 grid(N_DIM / 128, C_DIM / 128, B);
        pgemm_kernel<false, false, 1, 1, 0><<<grid, 256, smQKV>>>(
            wh + 3 * CC, wl + 3 * CC, oh, ol,
            out, (__half*)0, (__half*)0, (__half*)0, (__half*)0, (__half*)0,
            C_DIM, C_DIM, N_DIM, N_DIM, 0, CN, CN,
            bp, (const float*)0, (const float*)0, x, CN, 1.0f);
    }
}

// round 10
// speedup vs baseline: 5.0622x; 1.1149x over previous
#include <cuda_runtime.h>
#include <cuda_fp16.h>
#include <stdint.h>
#include <math.h>

typedef unsigned int u32;

#define C_DIM 512
#define N_DIM 4096
#define MAXB  4

// -------- scratch (__device__ globals) --------------------------------------
__device__ __half g_xh[MAXB * C_DIM * N_DIM];   // xn hi
__device__ __half g_xl[MAXB * C_DIM * N_DIM];   // xn lo
__device__ __half g_qs[MAXB * C_DIM * N_DIM];   // q single fp16
__device__ __half g_ks[MAXB * C_DIM * N_DIM];   // k single fp16
__device__ __half g_vs[MAXB * C_DIM * N_DIM];   // v single fp16
__device__ __half g_vps[MAXB * C_DIM * N_DIM];  // V' = Wp.v single fp16
__device__ __half g_wh[4 * C_DIM * C_DIM];      // weights hi (q,k,v,p stacked)
__device__ __half g_wl[4 * C_DIM * C_DIM];      // weights lo
__device__ __half g_attn[MAXB * (size_t)N_DIM * N_DIM];  // S fp16 (134 MB)
__device__ __half g_ps[MAXB * (size_t)N_DIM * N_DIM];    // P fp16 (134 MB)

// ============================================================================
// Helpers
// ============================================================================
__device__ __forceinline__ void split_store2(__half* Ch, __half* Cl,
                                             size_t o, float x, float y)
{
    __half hx = __float2half(x);
    __half hy = __float2half(y);
    __half lx = __float2half(x - __half2float(hx));
    __half ly = __float2half(y - __half2float(hy));
    __half2 th(hx, hy);
    __half2 tl(lx, ly);
    *(u32*)&Ch[o] = *(u32*)&th;
    *(u32*)&Cl[o] = *(u32*)&tl;
}

__device__ __forceinline__ void single_store2(__half* C, size_t o, float x, float y)
{
    __half2 t(__float2half(x), __float2half(y));
    *(u32*)&C[o] = *(u32*)&t;
}

__device__ __forceinline__ u32 saddr(const void* p)
{
    return (u32)__cvta_generic_to_shared(p);
}

__device__ __forceinline__ void cp16(u32 dst, const void* src)
{
    asm volatile("cp.async.cg.shared.global [%0], [%1], 16;\n" :: "r"(dst), "l"(src));
}
__device__ __forceinline__ void cp_commit()
{
    asm volatile("cp.async.commit_group;\n");
}
template <int NN_>
__device__ __forceinline__ void cp_wait()
{
    asm volatile("cp.async.wait_group %0;\n" :: "n"(NN_));
}

__device__ __forceinline__ void ldsm4(u32* r, u32 a)
{
    asm volatile("ldmatrix.sync.aligned.m8n8.x4.shared.b16 {%0,%1,%2,%3}, [%4];\n"
        : "=r"(r[0]), "=r"(r[1]), "=r"(r[2]), "=r"(r[3]) : "r"(a));
}
__device__ __forceinline__ void ldsm4t(u32* r, u32 a)
{
    asm volatile("ldmatrix.sync.aligned.m8n8.x4.trans.shared.b16 {%0,%1,%2,%3}, [%4];\n"
        : "=r"(r[0]), "=r"(r[1]), "=r"(r[2]), "=r"(r[3]) : "r"(a));
}
__device__ __forceinline__ void mma_f16(float* c, const u32* a, u32 b0, u32 b1)
{
    asm volatile(
        "mma.sync.aligned.m16n8k16.row.col.f32.f16.f16.f32 "
        "{%0,%1,%2,%3}, {%4,%5,%6,%7}, {%8,%9}, {%0,%1,%2,%3};\n"
        : "+f"(c[0]), "+f"(c[1]), "+f"(c[2]), "+f"(c[3])
        : "r"(a[0]), "r"(a[1]), "r"(a[2]), "r"(a[3]), "r"(b0), "r"(b1));
}

// ============================================================================
// fp32 -> split fp16 (weights)
// ============================================================================
__global__ void split_kernel(const float* __restrict__ in,
                             __half* __restrict__ h,
                             __half* __restrict__ l, int n4)
{
    int i = blockIdx.x * blockDim.x + threadIdx.x;
    if (i >= n4) return;
    float4 v = ((const float4*)in)[i];
    split_store2(h, l, (size_t)i * 4,     v.x, v.y);
    split_store2(h, l, (size_t)i * 4 + 2, v.z, v.w);
}

// ============================================================================
// GroupNorm: 32 groups, 16 ch/group, eps=1e-5; writes split fp16
// ============================================================================
__global__ void groupnorm_kernel(const float* __restrict__ x,
                                 const float* __restrict__ w,
                                 const float* __restrict__ b,
                                 __half* __restrict__ oh,
                                 __half* __restrict__ ol)
{
    const int CPG = 16;
    const int CNT = CPG * N_DIM;
    int bg = blockIdx.x;
    int g  = bg & 31;
    int bb = bg >> 5;
    size_t base = ((size_t)bb * C_DIM + (size_t)g * CPG) * N_DIM;
    const float4* x4 = (const float4*)(x + base);
    int tid = threadIdx.x;

    float s = 0.f, ss = 0.f;
    for (int i = tid; i < CNT / 4; i += blockDim.x) {
        float4 v = x4[i];
        s  += v.x + v.y + v.z + v.w;
        ss += v.x * v.x + v.y * v.y + v.z * v.z + v.w * v.w;
    }
    __shared__ float rs[8], rss[8];
    #pragma unroll
    for (int o = 16; o; o >>= 1) {
        s  += __shfl_xor_sync(0xffffffffu, s,  o);
        ss += __shfl_xor_sync(0xffffffffu, ss, o);
    }
    int wid = tid >> 5;
    int lid = tid & 31;
    if (lid == 0) { rs[wid] = s; rss[wid] = ss; }
    __syncthreads();
    if (tid == 0) {
        float ts = 0.f, tss = 0.f;
        int nw = blockDim.x >> 5;
        for (int i = 0; i < nw; i++) { ts += rs[i]; tss += rss[i]; }
        rs[0] = ts; rss[0] = tss;
    }
    __syncthreads();
    float mu   = rs[0] / (float)CNT;
    float var  = rss[0] / (float)CNT - mu * mu;
    float rsig = rsqrtf(var + 1e-5f);

    for (int i = tid; i < CNT / 4; i += blockDim.x) {
        int c = g * CPG + (i >> 10);
        float sc = w[c] * rsig;
        float sh = b[c] - mu * sc;
        float4 v = x4[i];
        size_t o = base + (size_t)i * 4;
        split_store2(oh, ol, o,     v.x * sc + sh, v.y * sc + sh);
        split_store2(oh, ol, o + 2, v.z * sc + sh, v.w * sc + sh);
    }
}

// ============================================================================
// Pipelined fp16 tensor-core GEMM (cp.async, 2 stages, 2 CTAs/SM).
//   C[m,n] = alpha * sum_k A(m,k)*B(k,n)
//   ASP/BSP: operand has a lo compensation term (adds 1 MMA each).
//   TA/TB: storage orientation. BK: 32 or 64.
//   OMODE: 0 = fp32 out (+row bias, +res)
//          1 = single fp16 out (Ch) (+row bias)
//          2 = fused-QKV routing (blockIdx.y: 0-3=q,4-7=k,8-11=v; single out)
// Conflict-free smem strides: !TA / TB=1 rows: 56 (BK32) or 72 (BK64);
// TA / !TB rows: 136.
// ============================================================================
#define NSTAGE 2

template <bool TA, bool TB, int ASP, int BSP, int OMODE, int BK>
__global__ __launch_bounds__(256, 2)
void pgemm_kernel(const __half* __restrict__ Agh,
                  const __half* __restrict__ Agl,
                  const __half* __restrict__ Bgh,
                  const __half* __restrict__ Bgl,
                  float* __restrict__ Cf,
                  __half* __restrict__ Ch,
                  __half* __restrict__ Qs,
                  __half* __restrict__ Ks,
                  __half* __restrict__ Vs,
                  int K, int lda, int ldb, int ldc,
                  long long sA, long long sB, long long sC,
                  const float* __restrict__ bias,
                  const float* __restrict__ bias2,
                  const float* __restrict__ bias3,
                  const float* __restrict__ res, long long sRes,
                  float alpha)
{
    const int PAD = (BK == 32) ? 56 : (BK + 8);
    const int AST = TA ? 136 : PAD;
    const int BST = TB ? PAD : 136;
    const int ASZ = TA ? (BK * AST) : (128 * AST);
    const int BSZ = TB ? (128 * BST) : (BK * BST);
    const int STAGE = (1 + ASP) * ASZ + (1 + BSP) * BSZ;
    const int KD = BK / 8;          // cp16s per row (narrow dim)
    const int RIT = BK / 16;        // load iterations per operand

    extern __shared__ __align__(16) char smraw[];
    __half* sm = (__half*)smraw;

    int z = blockIdx.z;
    Agh += (long long)z * sA;
    if (ASP) Agl += (long long)z * sA;
    Bgh += (long long)z * sB;
    if (BSP) Bgl += (long long)z * sB;

    int sel = 0;
    int m0;
    if (OMODE == 2) {
        sel = blockIdx.y >> 2;
        m0  = (blockIdx.y & 3) * 128;
        long long wo = (long long)sel * C_DIM * C_DIM;
        Agh += wo;
        if (ASP) Agl += wo;
        Qs += (long long)z * sC;
        Ks += (long long)z * sC;
        Vs += (long long)z * sC;
    } else {
        m0 = blockIdx.y * 128;
        if (OMODE == 1) Ch += (long long)z * sC;
        else            Cf += (long long)z * sC;
        if (OMODE == 0 && res) res += (long long)z * sRes;
    }

    int n0 = blockIdx.x * 128;
    int tid  = threadIdx.x;
    int lane = tid & 31;
    int wid  = tid >> 5;
    int m_w = (wid >> 2) * 64;
    int n_w = (wid & 3) * 32;

    int a_base, b_base;
    if (!TA) {
        a_base = (m_w + (lane & 15)) * AST + ((lane >> 4) * 8);
    } else {
        a_base = (((lane >> 4) & 1) * 8 + (lane & 7)) * AST
               + m_w + ((lane >> 3) & 1) * 8;
    }
    if (!TB) {
        b_base = (((lane >> 3) & 1) * 8 + (lane & 7)) * BST
               + n_w + ((lane >> 4) & 1) * 8;
    } else {
        b_base = (n_w + ((lane >> 4) & 1) * 8 + (lane & 7)) * BST
               + ((lane >> 3) & 1) * 8;
    }

    float c[4][4][4];
    #pragma unroll
    for (int i = 0; i < 4; i++) {
        #pragma unroll
        for (int j = 0; j < 4; j++) {
            #pragma unroll
            for (int t = 0; t < 4; t++) c[i][j][t] = 0.f;
        }
    }

    int KT = K / BK;

    auto load_stage = [&](int st, int k0) {
        __half* sAh = sm + st * STAGE;
        __half* sAl = sAh + ASZ;
        __half* sBh = sAh + (1 + ASP) * ASZ;
        __half* sBl = sBh + BSZ;
        #pragma unroll
        for (int r = 0; r < RIT; r++) {
            int i = tid + r * 256;
            if (!TA) {
                int m  = i / KD;
                int kq = (i % KD) * 8;
                size_t go = (size_t)(m0 + m) * lda + k0 + kq;
                int    so = m * AST + kq;
                cp16(saddr(sAh + so), Agh + go);
                if (ASP) cp16(saddr(sAl + so), Agl + go);
            } else {
                int k  = i >> 4;
                int mq = (i & 15) * 8;
                size_t go = (size_t)(k0 + k) * lda + m0 + mq;
                int    so = k * AST + mq;
                cp16(saddr(sAh + so), Agh + go);
                if (ASP) cp16(saddr(sAl + so), Agl + go);
            }
            if (!TB) {
                int k  = i >> 4;
                int nq = (i & 15) * 8;
                size_t go = (size_t)(k0 + k) * ldb + n0 + nq;
                int    so = k * BST + nq;
                cp16(saddr(sBh + so), Bgh + go);
                if (BSP) cp16(saddr(sBl + so), Bgl + go);
            } else {
                int n  = i / KD;
                int kq = (i % KD) * 8;
                size_t go = (size_t)(n0 + n) * ldb + k0 + kq;
                int    so = n * BST + kq;
                cp16(saddr(sBh + so), Bgh + go);
                if (BSP) cp16(saddr(sBl + so), Bgl + go);
            }
        }
    };

    #pragma unroll
    for (int s = 0; s < NSTAGE - 1; s++) {
        if (s < KT) load_stage(s, s * BK);
        cp_commit();
    }

    for (int kt = 0; kt < KT; kt++) {
        cp_wait<NSTAGE - 2>();
        __syncthreads();

        int pf = kt + NSTAGE - 1;
        if (pf < KT) load_stage(pf % NSTAGE, pf * BK);
        cp_commit();

        int st = kt % NSTAGE;
        const __half* pAh = sm + st * STAGE;
        const __half* pAl = pAh + ASZ;
        const __half* pBh = pAh + (1 + ASP) * ASZ;
        const __half* pBl = pBh + BSZ;

        #pragma unroll
        for (int ks = 0; ks < BK / 16; ks++) {
            int aoff = a_base + (TA ? ks * 16 * AST : ks * 16);
            int boff = b_base + (TB ? ks * 16 : ks * 16 * BST);

            u32 ah[4][4], al[4][4], bh[2][4], bl[2][4];
            #pragma unroll
            for (int mt = 0; mt < 4; mt++) {
                int o = aoff + (TA ? mt * 16 : mt * 16 * AST);
                if (TA) {
                    ldsm4t(ah[mt], saddr(pAh + o));
                    if (ASP) ldsm4t(al[mt], saddr(pAl + o));
                } else {
                    ldsm4(ah[mt], saddr(pAh + o));
                    if (ASP) ldsm4(al[mt], saddr(pAl + o));
                }
            }
            #pragma unroll
            for (int p = 0; p < 2; p++) {
                int o = boff + (TB ? p * 16 * BST : p * 16);
                if (TB) {
                    ldsm4(bh[p], saddr(pBh + o));
                    if (BSP) ldsm4(bl[p], saddr(pBl + o));
                } else {
                    ldsm4t(bh[p], saddr(pBh + o));
                    if (BSP) ldsm4t(bl[p], saddr(pBl + o));
                }
            }
            #pragma unroll
            for (int mt = 0; mt < 4; mt++) {
                #pragma unroll
                for (int nt = 0; nt < 4; nt++) {
                    int p = nt >> 1;
                    int q = (nt & 1) * 2;
                    mma_f16(c[mt][nt], ah[mt], bh[p][q], bh[p][q + 1]);
                    if (BSP) mma_f16(c[mt][nt], ah[mt], bl[p][q], bl[p][q + 1]);
                    if (ASP) mma_f16(c[mt][nt], al[mt], bh[p][q], bh[p][q + 1]);
                }
            }
        }
        __syncthreads();
    }

    // ---- epilogue ----
    const float* bp_ = bias;
    __half* So = (OMODE == 1) ? Ch : Qs;
    if (OMODE == 2) {
        if (sel == 1)      { bp_ = bias2; So = Ks; }
        else if (sel == 2) { bp_ = bias3; So = Vs; }
    }

    int g  = lane >> 2;
    int tq = lane & 3;
    #pragma unroll
    for (int mt = 0; mt < 4; mt++) {
        int mr0 = m0 + m_w + mt * 16 + g;
        int mr1 = mr0 + 8;
        float b0v = bp_ ? bp_[mr0] : 0.f;
        float b1v = bp_ ? bp_[mr1] : 0.f;
        #pragma unroll
        for (int nt = 0; nt < 4; nt++) {
            int nc = n0 + n_w + nt * 8 + tq * 2;
            size_t o0 = (size_t)mr0 * ldc + nc;
            size_t o1 = (size_t)mr1 * ldc + nc;
            float v00 = c[mt][nt][0] * alpha + b0v;
            float v01 = c[mt][nt][1] * alpha + b0v;
            float v10 = c[mt][nt][2] * alpha + b1v;
            float v11 = c[mt][nt][3] * alpha + b1v;
            if (OMODE == 0) {
                if (res) {
                    float2 r0 = *(const float2*)&res[o0];
                    float2 r1 = *(const float2*)&res[o1];
                    v00 += r0.x; v01 += r0.y;
                    v10 += r1.x; v11 += r1.y;
                }
                float2 w0; w0.x = v00; w0.y = v01;
                float2 w1; w1.x = v10; w1.y = v11;
                *(float2*)&Cf[o0] = w0;
                *(float2*)&Cf[o1] = w1;
            } else {
                single_store2(So, o0, v00, v01);
                single_store2(So, o1, v10, v11);
            }
        }
    }
}

// ============================================================================
// Row softmax over fp16 attn[b,i,:] (4096), writes fp16 P.
// ============================================================================
__global__ void softmax_kernel(const __half* __restrict__ attn,
                               __half* __restrict__ ps)
{
    size_t row = blockIdx.x;
    const uint4* p = (const uint4*)(attn + row * N_DIM);
    uint4* q = (uint4*)(ps + row * N_DIM);
    int tid = threadIdx.x;
    __shared__ float sh[8];

    float v[2][8];
    float mx = -1e30f;
    #pragma unroll
    for (int i = 0; i < 2; i++) {
        uint4 u = p[tid + i * 256];
        u32 w[4] = {u.x, u.y, u.z, u.w};
        #pragma unroll
        for (int j = 0; j < 4; j++) {
            float2 f = __half22float2(*(__half2*)&w[j]);
            v[i][j * 2]     = f.x;
            v[i][j * 2 + 1] = f.y;
            mx = fmaxf(mx, fmaxf(f.x, f.y));
        }
    }
    #pragma unroll
    for (int o = 16; o; o >>= 1) mx = fmaxf(mx, __shfl_xor_sync(0xffffffffu, mx, o));
    if ((tid & 31) == 0) sh[tid >> 5] = mx;
    __syncthreads();
    if (tid == 0) {
        float t = sh[0];
        for (int i = 1; i < 8; i++) t = fmaxf(t, sh[i]);
        sh[0] = t;
    }
    __syncthreads();
    mx = sh[0];
    __syncthreads();

    float sum = 0.f;
    #pragma unroll
    for (int i = 0; i < 2; i++) {
        #pragma unroll
        for (int j = 0; j < 8; j++) {
            v[i][j] = __expf(v[i][j] - mx);
            sum += v[i][j];
        }
    }
    #pragma unroll
    for (int o = 16; o; o >>= 1) sum += __shfl_xor_sync(0xffffffffu, sum, o);
    if ((tid & 31) == 0) sh[tid >> 5] = sum;
    __syncthreads();
    if (tid == 0) {
        float t = 0.f;
        for (int i = 0; i < 8; i++) t += sh[i];
        sh[0] = t;
    }
    __syncthreads();
    float inv = 1.f / sh[0];

    #pragma unroll
    for (int i = 0; i < 2; i++) {
        uint4 u;
        u32* w = (u32*)&u;
        #pragma unroll
        for (int j = 0; j < 4; j++) {
            __half2 t(__float2half(v[i][j * 2] * inv),
                      __float2half(v[i][j * 2 + 1] * inv));
            w[j] = *(u32*)&t;
        }
        q[tid + i * 256] = u;
    }
}

// ============================================================================
// Host launcher
// ============================================================================
static int stage_elems(bool ta, bool tb, int asp, int bsp, int bk)
{
    int pad = (bk == 32) ? 56 : (bk + 8);
    int AST = ta ? 136 : pad;
    int BST = tb ? pad : 136;
    int ASZ = ta ? (bk * AST) : (128 * AST);
    int BSZ = tb ? (128 * BST) : (bk * BST);
    return (1 + asp) * ASZ + (1 + bsp) * BSZ;
}

extern "C" void kernel_launch(void* const* d_in, const int* in_sizes, int n_in,
                              void* d_out, int out_size)
{
    const float* x   = (const float*)d_in[0];
    const float* gnw = (const float*)d_in[1];
    const float* gnb = (const float*)d_in[2];
    const float* wq  = (const float*)d_in[3];
    const float* bq  = (const float*)d_in[4];
    const float* wk  = (const float*)d_in[5];
    const float* bk  = (const float*)d_in[6];
    const float* wv  = (const float*)d_in[7];
    const float* bv  = (const float*)d_in[8];
    const float* wp  = (const float*)d_in[9];
    const float* bp  = (const float*)d_in[10];
    float* out = (float*)d_out;

    int B = in_sizes[0] / (C_DIM * N_DIM);
    if (B < 1) B = 1;
    if (B > MAXB) B = MAXB;

    __half *xh, *xl, *qs, *ks, *vs, *vps, *wh, *wl, *attn, *ps;
    cudaGetSymbolAddress((void**)&xh,  g_xh);
    cudaGetSymbolAddress((void**)&xl,  g_xl);
    cudaGetSymbolAddress((void**)&qs,  g_qs);
    cudaGetSymbolAddress((void**)&ks,  g_ks);
    cudaGetSymbolAddress((void**)&vs,  g_vs);
    cudaGetSymbolAddress((void**)&vps, g_vps);
    cudaGetSymbolAddress((void**)&wh,  g_wh);
    cudaGetSymbolAddress((void**)&wl,  g_wl);
    cudaGetSymbolAddress((void**)&attn, g_attn);
    cudaGetSymbolAddress((void**)&ps,  g_ps);

    const long long CN = (long long)C_DIM * N_DIM;
    const long long NN = (long long)N_DIM * N_DIM;
    const long long CC = (long long)C_DIM * C_DIM;
    const float scale = 1.0f / sqrtf((float)C_DIM);

    int smQKV = NSTAGE * stage_elems(false, false, 1, 1, 32) * 2;
    int smS   = NSTAGE * stage_elems(true,  false, 0, 0, 64) * 2;
    int smVP  = NSTAGE * stage_elems(false, false, 1, 0, 32) * 2;
    int smPV  = NSTAGE * stage_elems(false, true,  0, 0, 64) * 2;
    cudaFuncSetAttribute(pgemm_kernel<false, false, 1, 1, 2, 32>,
                         cudaFuncAttributeMaxDynamicSharedMemorySize, smQKV);
    cudaFuncSetAttribute(pgemm_kernel<true, false, 0, 0, 1, 64>,
                         cudaFuncAttributeMaxDynamicSharedMemorySize, smS);
    cudaFuncSetAttribute(pgemm_kernel<false, false, 1, 0, 1, 32>,
                         cudaFuncAttributeMaxDynamicSharedMemorySize, smVP);
    cudaFuncSetAttribute(pgemm_kernel<false, true, 0, 0, 0, 64>,
                         cudaFuncAttributeMaxDynamicSharedMemorySize, smPV);

    // 1) GroupNorm -> split xn
    groupnorm_kernel<<<B * 32, 256>>>(x, gnw, gnb, xh, xl);

    // 2) Split the 4 weight matrices (q,k,v,p stacked)
    {
        int n4 = C_DIM * C_DIM / 4;
        int tb = 256, gb = (n4 + tb - 1) / tb;
        split_kernel<<<gb, tb>>>(wq, wh + 0 * CC, wl + 0 * CC, n4);
        split_kernel<<<gb, tb>>>(wk, wh + 1 * CC, wl + 1 * CC, n4);
        split_kernel<<<gb, tb>>>(wv, wh + 2 * CC, wl + 2 * CC, n4);
        split_kernel<<<gb, tb>>>(wp, wh + 3 * CC, wl + 3 * CC, n4);
    }

    // 3) Fused QKV projection (3-term): outputs single fp16 q/k/v
    {
        dim3 grid(N_DIM / 128, 12, B);
        pgemm_kernel<false, false, 1, 1, 2, 32><<<grid, 256, smQKV>>>(
            wh, wl, xh, xl,
            (float*)0, (__half*)0, qs, ks, vs,
            C_DIM, C_DIM, N_DIM, N_DIM, 0, CN, CN,
            bq, bk, bv, (const float*)0, 0, 1.0f);
    }

    // 4) Scores (1-term, BK=64): attn[i,j] = fp16(scale * sum_c q[c,i] k[c,j])
    {
        dim3 grid(N_DIM / 128, N_DIM / 128, B);
        pgemm_kernel<true, false, 0, 0, 1, 64><<<grid, 256, smS>>>(
            qs, (const __half*)0, ks, (const __half*)0,
            (float*)0, attn, (__half*)0, (__half*)0, (__half*)0,
            C_DIM, N_DIM, N_DIM, N_DIM, CN, CN, NN,
            (const float*)0, (const float*)0, (const float*)0,
            (const float*)0, 0, scale);
    }

    // 5) V' = Wp . v  (2-term: Wp split, v single) -> single fp16
    {
        dim3 grid(N_DIM / 128, C_DIM / 128, B);
        pgemm_kernel<false, false, 1, 0, 1, 32><<<grid, 256, smVP>>>(
            wh + 3 * CC, wl + 3 * CC, vs, (const __half*)0,
            (float*)0, vps, (__half*)0, (__half*)0, (__half*)0,
            C_DIM, C_DIM, N_DIM, N_DIM, 0, CN, CN,
            (const float*)0, (const float*)0, (const float*)0,
            (const float*)0, 0, 1.0f);
    }

    // 6) Softmax -> fp16 P
    softmax_kernel<<<B * N_DIM, 256>>>(attn, ps);

    // 7) Final (1-term, BK=64): out[c,i] = sum_j V'[c,j] P[i,j] + bp[c] + x[c,i]
    {
        dim3 grid(N_DIM / 128, C_DIM / 128, B);
        pgemm_kernel<false, true, 0, 0, 0, 64><<<grid, 256, smPV>>>(
            vps, (const __half*)0, ps, (const __half*)0,
            out, (__half*)0, (__half*)0, (__half*)0, (__half*)0,
            N_DIM, N_DIM, N_DIM, N_DIM, CN, NN, CN,
            bp, (const float*)0, (const float*)0, x, CN, 1.0f);
    }
}

// round 11
// speedup vs baseline: 5.4784x; 1.0822x over previous
#include <cuda_runtime.h>
#include <cuda_fp16.h>
#include <stdint.h>
#include <math.h>

typedef unsigned int u32;

#define C_DIM 512
#define N_DIM 4096
#define MAXB  4

// -------- scratch (__device__ globals) --------------------------------------
__device__ __half g_xs[MAXB * C_DIM * N_DIM];   // xn single fp16
__device__ __half g_qs[MAXB * C_DIM * N_DIM];   // q single fp16
__device__ __half g_ks[MAXB * C_DIM * N_DIM];   // k single fp16
__device__ __half g_vs[MAXB * C_DIM * N_DIM];   // v single fp16
__device__ __half g_vps[MAXB * C_DIM * N_DIM];  // V' = Wp.v single fp16
__device__ __half g_wh[4 * C_DIM * C_DIM];      // weights hi (q,k,v,p stacked)
__device__ __half g_wl[4 * C_DIM * C_DIM];      // weights lo
__device__ __half g_attn[MAXB * (size_t)N_DIM * N_DIM];  // S fp16 (134 MB)
__device__ __half g_ps[MAXB * (size_t)N_DIM * N_DIM];    // P fp16 (134 MB)

// ============================================================================
// Helpers
// ============================================================================
__device__ __forceinline__ void split_store2(__half* Ch, __half* Cl,
                                             size_t o, float x, float y)
{
    __half hx = __float2half(x);
    __half hy = __float2half(y);
    __half lx = __float2half(x - __half2float(hx));
    __half ly = __float2half(y - __half2float(hy));
    __half2 th(hx, hy);
    __half2 tl(lx, ly);
    *(u32*)&Ch[o] = *(u32*)&th;
    *(u32*)&Cl[o] = *(u32*)&tl;
}

__device__ __forceinline__ void single_store2(__half* C, size_t o, float x, float y)
{
    __half2 t(__float2half(x), __float2half(y));
    *(u32*)&C[o] = *(u32*)&t;
}

__device__ __forceinline__ u32 saddr(const void* p)
{
    return (u32)__cvta_generic_to_shared(p);
}

__device__ __forceinline__ void cp16(u32 dst, const void* src)
{
    asm volatile("cp.async.cg.shared.global [%0], [%1], 16;\n" :: "r"(dst), "l"(src));
}
__device__ __forceinline__ void cp_commit()
{
    asm volatile("cp.async.commit_group;\n");
}
template <int NN_>
__device__ __forceinline__ void cp_wait()
{
    asm volatile("cp.async.wait_group %0;\n" :: "n"(NN_));
}

__device__ __forceinline__ void ldsm4(u32* r, u32 a)
{
    asm volatile("ldmatrix.sync.aligned.m8n8.x4.shared.b16 {%0,%1,%2,%3}, [%4];\n"
        : "=r"(r[0]), "=r"(r[1]), "=r"(r[2]), "=r"(r[3]) : "r"(a));
}
__device__ __forceinline__ void ldsm4t(u32* r, u32 a)
{
    asm volatile("ldmatrix.sync.aligned.m8n8.x4.trans.shared.b16 {%0,%1,%2,%3}, [%4];\n"
        : "=r"(r[0]), "=r"(r[1]), "=r"(r[2]), "=r"(r[3]) : "r"(a));
}
__device__ __forceinline__ void mma_f16(float* c, const u32* a, u32 b0, u32 b1)
{
    asm volatile(
        "mma.sync.aligned.m16n8k16.row.col.f32.f16.f16.f32 "
        "{%0,%1,%2,%3}, {%4,%5,%6,%7}, {%8,%9}, {%0,%1,%2,%3};\n"
        : "+f"(c[0]), "+f"(c[1]), "+f"(c[2]), "+f"(c[3])
        : "r"(a[0]), "r"(a[1]), "r"(a[2]), "r"(a[3]), "r"(b0), "r"(b1));
}

// ============================================================================
// fp32 -> split fp16, all 4 weight matrices in one launch (grid.y = matrix)
// ============================================================================
__global__ void split4_kernel(const float* __restrict__ wq,
                              const float* __restrict__ wk,
                              const float* __restrict__ wv,
                              const float* __restrict__ wp,
                              __half* __restrict__ h,
                              __half* __restrict__ l, int n4)
{
    int i = blockIdx.x * blockDim.x + threadIdx.x;
    if (i >= n4) return;
    int sel = blockIdx.y;
    const float* in = (sel == 0) ? wq : (sel == 1) ? wk : (sel == 2) ? wv : wp;
    size_t off = (size_t)sel * n4 * 4;
    float4 v = ((const float4*)in)[i];
    split_store2(h + off, l + off, (size_t)i * 4,     v.x, v.y);
    split_store2(h + off, l + off, (size_t)i * 4 + 2, v.z, v.w);
}

// ============================================================================
// GroupNorm: 32 groups, 16 ch/group, eps=1e-5; writes single fp16
// ============================================================================
__global__ void groupnorm_kernel(const float* __restrict__ x,
                                 const float* __restrict__ w,
                                 const float* __restrict__ b,
                                 __half* __restrict__ os)
{
    const int CPG = 16;
    const int CNT = CPG * N_DIM;
    int bg = blockIdx.x;
    int g  = bg & 31;
    int bb = bg >> 5;
    size_t base = ((size_t)bb * C_DIM + (size_t)g * CPG) * N_DIM;
    const float4* x4 = (const float4*)(x + base);
    int tid = threadIdx.x;

    float s = 0.f, ss = 0.f;
    for (int i = tid; i < CNT / 4; i += blockDim.x) {
        float4 v = x4[i];
        s  += v.x + v.y + v.z + v.w;
        ss += v.x * v.x + v.y * v.y + v.z * v.z + v.w * v.w;
    }
    __shared__ float rs[8], rss[8];
    #pragma unroll
    for (int o = 16; o; o >>= 1) {
        s  += __shfl_xor_sync(0xffffffffu, s,  o);
        ss += __shfl_xor_sync(0xffffffffu, ss, o);
    }
    int wid = tid >> 5;
    int lid = tid & 31;
    if (lid == 0) { rs[wid] = s; rss[wid] = ss; }
    __syncthreads();
    if (tid == 0) {
        float ts = 0.f, tss = 0.f;
        int nw = blockDim.x >> 5;
        for (int i = 0; i < nw; i++) { ts += rs[i]; tss += rss[i]; }
        rs[0] = ts; rss[0] = tss;
    }
    __syncthreads();
    float mu   = rs[0] / (float)CNT;
    float var  = rss[0] / (float)CNT - mu * mu;
    float rsig = rsqrtf(var + 1e-5f);

    for (int i = tid; i < CNT / 4; i += blockDim.x) {
        int c = g * CPG + (i >> 10);
        float sc = w[c] * rsig;
        float sh = b[c] - mu * sc;
        float4 v = x4[i];
        size_t o = base + (size_t)i * 4;
        single_store2(os, o,     v.x * sc + sh, v.y * sc + sh);
        single_store2(os, o + 2, v.z * sc + sh, v.w * sc + sh);
    }
}

// ============================================================================
// Pipelined fp16 tensor-core GEMM (cp.async, NST stages, 2 CTAs/SM).
//   C[m,n] = alpha * sum_k A(m,k)*B(k,n)
//   ASP/BSP: operand has a lo compensation term (adds 1 MMA each).
//   TA/TB: storage orientation. BK: 32 or 64. NST: pipeline stages.
//   OMODE: 0 = fp32 out (+row bias, +res)
//          1 = single fp16 out (Ch) (+row bias)
//          2 = fused-QKV routing (blockIdx.y: 0-3=q,4-7=k,8-11=v; single out)
// Conflict-free smem strides: narrow rows 56 (BK32) / 72 (BK64); wide rows 136.
// ============================================================================
template <bool TA, bool TB, int ASP, int BSP, int OMODE, int BK, int NST>
__global__ __launch_bounds__(256, 2)
void pgemm_kernel(const __half* __restrict__ Agh,
                  const __half* __restrict__ Agl,
                  const __half* __restrict__ Bgh,
                  const __half* __restrict__ Bgl,
                  float* __restrict__ Cf,
                  __half* __restrict__ Ch,
                  __half* __restrict__ Qs,
                  __half* __restrict__ Ks,
                  __half* __restrict__ Vs,
                  int K, int lda, int ldb, int ldc,
                  long long sA, long long sB, long long sC,
                  const float* __restrict__ bias,
                  const float* __restrict__ bias2,
                  const float* __restrict__ bias3,
                  const float* __restrict__ res, long long sRes,
                  float alpha)
{
    const int PAD = (BK == 32) ? 56 : (BK + 8);
    const int AST = TA ? 136 : PAD;
    const int BST = TB ? PAD : 136;
    const int ASZ = TA ? (BK * AST) : (128 * AST);
    const int BSZ = TB ? (128 * BST) : (BK * BST);
    const int STAGE = (1 + ASP) * ASZ + (1 + BSP) * BSZ;
    const int KD = BK / 8;
    const int RIT = BK / 16;

    extern __shared__ __align__(16) char smraw[];
    __half* sm = (__half*)smraw;

    int z = blockIdx.z;
    Agh += (long long)z * sA;
    if (ASP) Agl += (long long)z * sA;
    Bgh += (long long)z * sB;
    if (BSP) Bgl += (long long)z * sB;

    int sel = 0;
    int m0;
    if (OMODE == 2) {
        sel = blockIdx.y >> 2;
        m0  = (blockIdx.y & 3) * 128;
        long long wo = (long long)sel * C_DIM * C_DIM;
        Agh += wo;
        if (ASP) Agl += wo;
        Qs += (long long)z * sC;
        Ks += (long long)z * sC;
        Vs += (long long)z * sC;
    } else {
        m0 = blockIdx.y * 128;
        if (OMODE == 1) Ch += (long long)z * sC;
        else            Cf += (long long)z * sC;
        if (OMODE == 0 && res) res += (long long)z * sRes;
    }

    int n0 = blockIdx.x * 128;
    int tid  = threadIdx.x;
    int lane = tid & 31;
    int wid  = tid >> 5;
    int m_w = (wid >> 2) * 64;
    int n_w = (wid & 3) * 32;

    int a_base, b_base;
    if (!TA) {
        a_base = (m_w + (lane & 15)) * AST + ((lane >> 4) * 8);
    } else {
        a_base = (((lane >> 4) & 1) * 8 + (lane & 7)) * AST
               + m_w + ((lane >> 3) & 1) * 8;
    }
    if (!TB) {
        b_base = (((lane >> 3) & 1) * 8 + (lane & 7)) * BST
               + n_w + ((lane >> 4) & 1) * 8;
    } else {
        b_base = (n_w + ((lane >> 4) & 1) * 8 + (lane & 7)) * BST
               + ((lane >> 3) & 1) * 8;
    }

    float c[4][4][4];
    #pragma unroll
    for (int i = 0; i < 4; i++) {
        #pragma unroll
        for (int j = 0; j < 4; j++) {
            #pragma unroll
            for (int t = 0; t < 4; t++) c[i][j][t] = 0.f;
        }
    }

    int KT = K / BK;

    auto load_stage = [&](int st, int k0) {
        __half* sAh = sm + st * STAGE;
        __half* sAl = sAh + ASZ;
        __half* sBh = sAh + (1 + ASP) * ASZ;
        __half* sBl = sBh + BSZ;
        #pragma unroll
        for (int r = 0; r < RIT; r++) {
            int i = tid + r * 256;
            if (!TA) {
                int m  = i / KD;
                int kq = (i % KD) * 8;
                size_t go = (size_t)(m0 + m) * lda + k0 + kq;
                int    so = m * AST + kq;
                cp16(saddr(sAh + so), Agh + go);
                if (ASP) cp16(saddr(sAl + so), Agl + go);
            } else {
                int k  = i >> 4;
                int mq = (i & 15) * 8;
                size_t go = (size_t)(k0 + k) * lda + m0 + mq;
                int    so = k * AST + mq;
                cp16(saddr(sAh + so), Agh + go);
                if (ASP) cp16(saddr(sAl + so), Agl + go);
            }
            if (!TB) {
                int k  = i >> 4;
                int nq = (i & 15) * 8;
                size_t go = (size_t)(k0 + k) * ldb + n0 + nq;
                int    so = k * BST + nq;
                cp16(saddr(sBh + so), Bgh + go);
                if (BSP) cp16(saddr(sBl + so), Bgl + go);
            } else {
                int n  = i / KD;
                int kq = (i % KD) * 8;
                size_t go = (size_t)(n0 + n) * ldb + k0 + kq;
                int    so = n * BST + kq;
                cp16(saddr(sBh + so), Bgh + go);
                if (BSP) cp16(saddr(sBl + so), Bgl + go);
            }
        }
    };

    #pragma unroll
    for (int s = 0; s < NST - 1; s++) {
        if (s < KT) load_stage(s, s * BK);
        cp_commit();
    }

    for (int kt = 0; kt < KT; kt++) {
        cp_wait<NST - 2>();
        __syncthreads();

        int pf = kt + NST - 1;
        if (pf < KT) load_stage(pf % NST, pf * BK);
        cp_commit();

        int st = kt % NST;
        const __half* pAh = sm + st * STAGE;
        const __half* pAl = pAh + ASZ;
        const __half* pBh = pAh + (1 + ASP) * ASZ;
        const __half* pBl = pBh + BSZ;

        #pragma unroll
        for (int ks = 0; ks < BK / 16; ks++) {
            int aoff = a_base + (TA ? ks * 16 * AST : ks * 16);
            int boff = b_base + (TB ? ks * 16 : ks * 16 * BST);

            u32 ah[4][4], al[4][4], bh[2][4], bl[2][4];
            #pragma unroll
            for (int mt = 0; mt < 4; mt++) {
                int o = aoff + (TA ? mt * 16 : mt * 16 * AST);
                if (TA) {
                    ldsm4t(ah[mt], saddr(pAh + o));
                    if (ASP) ldsm4t(al[mt], saddr(pAl + o));
                } else {
                    ldsm4(ah[mt], saddr(pAh + o));
                    if (ASP) ldsm4(al[mt], saddr(pAl + o));
                }
            }
            #pragma unroll
            for (int p = 0; p < 2; p++) {
                int o = boff + (TB ? p * 16 * BST : p * 16);
                if (TB) {
                    ldsm4(bh[p], saddr(pBh + o));
                    if (BSP) ldsm4(bl[p], saddr(pBl + o));
                } else {
                    ldsm4t(bh[p], saddr(pBh + o));
                    if (BSP) ldsm4t(bl[p], saddr(pBl + o));
                }
            }
            #pragma unroll
            for (int mt = 0; mt < 4; mt++) {
                #pragma unroll
                for (int nt = 0; nt < 4; nt++) {
                    int p = nt >> 1;
                    int q = (nt & 1) * 2;
                    mma_f16(c[mt][nt], ah[mt], bh[p][q], bh[p][q + 1]);
                    if (BSP) mma_f16(c[mt][nt], ah[mt], bl[p][q], bl[p][q + 1]);
                    if (ASP) mma_f16(c[mt][nt], al[mt], bh[p][q], bh[p][q + 1]);
                }
            }
        }
        __syncthreads();
    }

    // ---- epilogue ----
    const float* bp_ = bias;
    __half* So = (OMODE == 1) ? Ch : Qs;
    if (OMODE == 2) {
        if (sel == 1)      { bp_ = bias2; So = Ks; }
        else if (sel == 2) { bp_ = bias3; So = Vs; }
    }

    int g  = lane >> 2;
    int tq = lane & 3;
    #pragma unroll
    for (int mt = 0; mt < 4; mt++) {
        int mr0 = m0 + m_w + mt * 16 + g;
        int mr1 = mr0 + 8;
        float b0v = bp_ ? bp_[mr0] : 0.f;
        float b1v = bp_ ? bp_[mr1] : 0.f;
        #pragma unroll
        for (int nt = 0; nt < 4; nt++) {
            int nc = n0 + n_w + nt * 8 + tq * 2;
            size_t o0 = (size_t)mr0 * ldc + nc;
            size_t o1 = (size_t)mr1 * ldc + nc;
            float v00 = c[mt][nt][0] * alpha + b0v;
            float v01 = c[mt][nt][1] * alpha + b0v;
            float v10 = c[mt][nt][2] * alpha + b1v;
            float v11 = c[mt][nt][3] * alpha + b1v;
            if (OMODE == 0) {
                if (res) {
                    float2 r0 = *(const float2*)&res[o0];
                    float2 r1 = *(const float2*)&res[o1];
                    v00 += r0.x; v01 += r0.y;
                    v10 += r1.x; v11 += r1.y;
                }
                float2 w0; w0.x = v00; w0.y = v01;
                float2 w1; w1.x = v10; w1.y = v11;
                *(float2*)&Cf[o0] = w0;
                *(float2*)&Cf[o1] = w1;
            } else {
                single_store2(So, o0, v00, v01);
                single_store2(So, o1, v10, v11);
            }
        }
    }
}

// ============================================================================
// Row softmax over fp16 attn[b,i,:] (4096), writes fp16 P.
// ============================================================================
__global__ void softmax_kernel(const __half* __restrict__ attn,
                               __half* __restrict__ ps)
{
    size_t row = blockIdx.x;
    const uint4* p = (const uint4*)(attn + row * N_DIM);
    uint4* q = (uint4*)(ps + row * N_DIM);
    int tid = threadIdx.x;
    __shared__ float sh[8];

    float v[2][8];
    float mx = -1e30f;
    #pragma unroll
    for (int i = 0; i < 2; i++) {
        uint4 u = p[tid + i * 256];
        u32 w[4] = {u.x, u.y, u.z, u.w};
        #pragma unroll
        for (int j = 0; j < 4; j++) {
            float2 f = __half22float2(*(__half2*)&w[j]);
            v[i][j * 2]     = f.x;
            v[i][j * 2 + 1] = f.y;
            mx = fmaxf(mx, fmaxf(f.x, f.y));
        }
    }
    #pragma unroll
    for (int o = 16; o; o >>= 1) mx = fmaxf(mx, __shfl_xor_sync(0xffffffffu, mx, o));
    if ((tid & 31) == 0) sh[tid >> 5] = mx;
    __syncthreads();
    if (tid == 0) {
        float t = sh[0];
        for (int i = 1; i < 8; i++) t = fmaxf(t, sh[i]);
        sh[0] = t;
    }
    __syncthreads();
    mx = sh[0];
    __syncthreads();

    float sum = 0.f;
    #pragma unroll
    for (int i = 0; i < 2; i++) {
        #pragma unroll
        for (int j = 0; j < 8; j++) {
            v[i][j] = __expf(v[i][j] - mx);
            sum += v[i][j];
        }
    }
    #pragma unroll
    for (int o = 16; o; o >>= 1) sum += __shfl_xor_sync(0xffffffffu, sum, o);
    if ((tid & 31) == 0) sh[tid >> 5] = sum;
    __syncthreads();
    if (tid == 0) {
        float t = 0.f;
        for (int i = 0; i < 8; i++) t += sh[i];
        sh[0] = t;
    }
    __syncthreads();
    float inv = 1.f / sh[0];

    #pragma unroll
    for (int i = 0; i < 2; i++) {
        uint4 u;
        u32* w = (u32*)&u;
        #pragma unroll
        for (int j = 0; j < 4; j++) {
            __half2 t(__float2half(v[i][j * 2] * inv),
                      __float2half(v[i][j * 2 + 1] * inv));
            w[j] = *(u32*)&t;
        }
        q[tid + i * 256] = u;
    }
}

// ============================================================================
// Host launcher
// ============================================================================
static int stage_elems(bool ta, bool tb, int asp, int bsp, int bk)
{
    int pad = (bk == 32) ? 56 : (bk + 8);
    int AST = ta ? 136 : pad;
    int BST = tb ? pad : 136;
    int ASZ = ta ? (bk * AST) : (128 * AST);
    int BSZ = tb ? (128 * BST) : (bk * BST);
    return (1 + asp) * ASZ + (1 + bsp) * BSZ;
}

extern "C" void kernel_launch(void* const* d_in, const int* in_sizes, int n_in,
                              void* d_out, int out_size)
{
    const float* x   = (const float*)d_in[0];
    const float* gnw = (const float*)d_in[1];
    const float* gnb = (const float*)d_in[2];
    const float* wq  = (const float*)d_in[3];
    const float* bq  = (const float*)d_in[4];
    const float* wk  = (const float*)d_in[5];
    const float* bk  = (const float*)d_in[6];
    const float* wv  = (const float*)d_in[7];
    const float* bv  = (const float*)d_in[8];
    const float* wp  = (const float*)d_in[9];
    const float* bp  = (const float*)d_in[10];
    float* out = (float*)d_out;

    int B = in_sizes[0] / (C_DIM * N_DIM);
    if (B < 1) B = 1;
    if (B > MAXB) B = MAXB;

    __half *xs, *qs, *ks, *vs, *vps, *wh, *wl, *attn, *ps;
    cudaGetSymbolAddress((void**)&xs,  g_xs);
    cudaGetSymbolAddress((void**)&qs,  g_qs);
    cudaGetSymbolAddress((void**)&ks,  g_ks);
    cudaGetSymbolAddress((void**)&vs,  g_vs);
    cudaGetSymbolAddress((void**)&vps, g_vps);
    cudaGetSymbolAddress((void**)&wh,  g_wh);
    cudaGetSymbolAddress((void**)&wl,  g_wl);
    cudaGetSymbolAddress((void**)&attn, g_attn);
    cudaGetSymbolAddress((void**)&ps,  g_ps);

    const long long CN = (long long)C_DIM * N_DIM;
    const long long NN = (long long)N_DIM * N_DIM;
    const float scale = 1.0f / sqrtf((float)C_DIM);

    int smQKV = 2 * stage_elems(false, false, 1, 0, 32) * 2;
    int smS   = 3 * stage_elems(true,  false, 0, 0, 64) * 2;
    int smVP  = 2 * stage_elems(false, false, 1, 0, 32) * 2;
    int smPV  = 3 * stage_elems(false, true,  0, 0, 64) * 2;
    cudaFuncSetAttribute(pgemm_kernel<false, false, 1, 0, 2, 32, 2>,
                         cudaFuncAttributeMaxDynamicSharedMemorySize, smQKV);
    cudaFuncSetAttribute(pgemm_kernel<true, false, 0, 0, 1, 64, 3>,
                         cudaFuncAttributeMaxDynamicSharedMemorySize, smS);
    cudaFuncSetAttribute(pgemm_kernel<false, false, 1, 0, 1, 32, 2>,
                         cudaFuncAttributeMaxDynamicSharedMemorySize, smVP);
    cudaFuncSetAttribute(pgemm_kernel<false, true, 0, 0, 0, 64, 3>,
                         cudaFuncAttributeMaxDynamicSharedMemorySize, smPV);

    // 1) GroupNorm -> single fp16 xn
    groupnorm_kernel<<<B * 32, 256>>>(x, gnw, gnb, xs);

    // 2) Split all 4 weight matrices in one launch
    {
        int n4 = C_DIM * C_DIM / 4;
        dim3 grid((n4 + 255) / 256, 4);
        split4_kernel<<<grid, 256>>>(wq, wk, wv, wp, wh, wl, n4);
    }

    // 3) Fused QKV projection (2-term: W split, x single) -> single fp16 q/k/v
    {
        dim3 grid(N_DIM / 128, 12, B);
        pgemm_kernel<false, false, 1, 0, 2, 32, 2><<<grid, 256, smQKV>>>(
            wh, wl, xs, (const __half*)0,
            (float*)0, (__half*)0, qs, ks, vs,
            C_DIM, C_DIM, N_DIM, N_DIM, 0, CN, CN,
            bq, bk, bv, (const float*)0, 0, 1.0f);
    }

    // 4) Scores (1-term, BK=64, 3-stage): attn = fp16(scale * q^T k)
    {
        dim3 grid(N_DIM / 128, N_DIM / 128, B);
        pgemm_kernel<true, false, 0, 0, 1, 64, 3><<<grid, 256, smS>>>(
            qs, (const __half*)0, ks, (const __half*)0,
            (float*)0, attn, (__half*)0, (__half*)0, (__half*)0,
            C_DIM, N_DIM, N_DIM, N_DIM, CN, CN, NN,
            (const float*)0, (const float*)0, (const float*)0,
            (const float*)0, 0, scale);
    }

    // 5) V' = Wp . v  (2-term: Wp split, v single) -> single fp16
    {
        long long CC = (long long)C_DIM * C_DIM;
        dim3 grid(N_DIM / 128, C_DIM / 128, B);
        pgemm_kernel<false, false, 1, 0, 1, 32, 2><<<grid, 256, smVP>>>(
            wh + 3 * CC, wl + 3 * CC, vs, (const __half*)0,
            (float*)0, vps, (__half*)0, (__half*)0, (__half*)0,
            C_DIM, C_DIM, N_DIM, N_DIM, 0, CN, CN,
            (const float*)0, (const float*)0, (const float*)0,
            (const float*)0, 0, 1.0f);
    }

    // 6) Softmax -> fp16 P
    softmax_kernel<<<B * N_DIM, 256>>>(attn, ps);

    // 7) Final (1-term, BK=64, 3-stage): out = V'.P + bp + x
    {
        dim3 grid(N_DIM / 128, C_DIM / 128, B);
        pgemm_kernel<false, true, 0, 0, 0, 64, 3><<<grid, 256, smPV>>>(
            vps, (const __half*)0, ps, (const __half*)0,
            out, (__half*)0, (__half*)0, (__half*)0, (__half*)0,
            N_DIM, N_DIM, N_DIM, N_DIM, CN, NN, CN,
            bp, (const float*)0, (const float*)0, x, CN, 1.0f);
    }
}